// round 2
// baseline (speedup 1.0000x reference)
#include <cuda_runtime.h>
#include <cuda_bf16.h>

#define NN 16384
#define EE 524288
#define BG 8
#define FIN 26
#define DD 128
#define HH 256
#define NOUT 64
#define NL 4
#define NRBF 16

// ---------------- device scratch (statically allocated; no cudaMalloc) -------
__device__ float g_h[NN * DD];        // node features (residual stream)
__device__ float g_P[NN * HH];        // h @ W1a + b1
__device__ float g_Q[NN * HH];        // h @ W1b
__device__ float g_ef[EE * NRBF];     // edge RBF features
__device__ float g_agg[NN * DD];      // message aggregation
__device__ float g_gsum[BG * DD];     // per-graph sums

__device__ __forceinline__ float silu_f(float x) {
    return x / (1.f + __expf(-x));
}

// ---------------- embedding MLP: 26 -> 128 -> silu -> 128 -------------------
__global__ void __launch_bounds__(128) embed_kernel(
    const float* __restrict__ x, const float* __restrict__ W1,
    const float* __restrict__ b1, const float* __restrict__ W2,
    const float* __restrict__ b2)
{
    __shared__ float xs[4][FIN];
    __shared__ float hid[4][DD];
    int t = threadIdx.x;
    int n0 = blockIdx.x * 4;
    for (int i = t; i < 4 * FIN; i += 128)
        xs[i / FIN][i % FIN] = x[(size_t)n0 * FIN + i];
    __syncthreads();
    float b1t = b1[t];
    #pragma unroll
    for (int nd = 0; nd < 4; nd++) {
        float acc = b1t;
        #pragma unroll
        for (int k = 0; k < FIN; k++) acc += xs[nd][k] * W1[k * DD + t];
        hid[nd][t] = silu_f(acc);
    }
    __syncthreads();
    float b2t = b2[t];
    #pragma unroll
    for (int nd = 0; nd < 4; nd++) {
        float acc = b2t;
        for (int k = 0; k < DD; k++) acc += hid[nd][k] * W2[k * DD + t];
        g_h[(size_t)(n0 + nd) * DD + t] = acc;
    }
}

// ---------------- edge RBF ---------------------------------------------------
__global__ void __launch_bounds__(256) rbf_kernel(
    const float* __restrict__ pos, const int* __restrict__ ei)
{
    int e = blockIdx.x * blockDim.x + threadIdx.x;
    if (e >= EE) return;
    int s  = ei[e];
    int dd = ei[EE + e];
    float dx = pos[dd * 3 + 0] - pos[s * 3 + 0];
    float dy = pos[dd * 3 + 1] - pos[s * 3 + 1];
    float dz = pos[dd * 3 + 2] - pos[s * 3 + 2];
    float d = sqrtf(dx * dx + dy * dy + dz * dz + 1e-12f);
    float env = (d < 10.f) ? 0.5f * (cosf(0.31415926535897932f * d) + 1.f) : 0.f;
    #pragma unroll
    for (int i = 0; i < NRBF; i++) {
        float c = (10.f / 15.f) * (float)i;
        float u = d - c;
        g_ef[(size_t)e * NRBF + i] = env * __expf(-u * u * 1.28f);
    }
}

// ---------------- per-layer P/Q node GEMM: [P|Q] = h @ [W1a|W1b] (+b1 on P) --
__global__ void __launch_bounds__(256) pq_kernel(
    const float* __restrict__ W1, const float* __restrict__ b1, int l)
{
    __shared__ float hs[32 * DD];     // 16 KB
    int t = threadIdx.x;
    int n0 = blockIdx.x * 32;
    for (int i = t; i < 32 * DD / 4; i += 256)
        ((float4*)hs)[i] = ((const float4*)(g_h + (size_t)n0 * DD))[i];
    __syncthreads();

    int ng = t >> 6;          // 0..3 -> nodes ng*8..+7
    int cg = t & 63;          // col group -> cols cg*8 (0..511)
    int c0 = cg * 8;
    bool isP = (c0 < HH);
    const float* wp = isP ? (W1 + (size_t)(l * 272) * HH + c0)
                          : (W1 + (size_t)(l * 272 + 128) * HH + (c0 - HH));
    float acc[8][8];
    float bi[8];
    #pragma unroll
    for (int c = 0; c < 8; c++) bi[c] = isP ? b1[l * HH + c0 + c] : 0.f;
    #pragma unroll
    for (int r = 0; r < 8; r++)
        #pragma unroll
        for (int c = 0; c < 8; c++) acc[r][c] = bi[c];

    for (int k = 0; k < DD; k++) {
        float a[8];
        #pragma unroll
        for (int r = 0; r < 8; r++) a[r] = hs[(ng * 8 + r) * DD + k];
        float4 w0 = *(const float4*)(wp + (size_t)k * HH);
        float4 w1 = *(const float4*)(wp + (size_t)k * HH + 4);
        float wv[8] = {w0.x, w0.y, w0.z, w0.w, w1.x, w1.y, w1.z, w1.w};
        #pragma unroll
        for (int r = 0; r < 8; r++)
            #pragma unroll
            for (int c = 0; c < 8; c++) acc[r][c] += a[r] * wv[c];
    }
    #pragma unroll
    for (int r = 0; r < 8; r++) {
        int n = n0 + ng * 8 + r;
        float* dp = isP ? (g_P + (size_t)n * HH + c0)
                        : (g_Q + (size_t)n * HH + (c0 - HH));
        *(float4*)(dp)     = make_float4(acc[r][0], acc[r][1], acc[r][2], acc[r][3]);
        *(float4*)(dp + 4) = make_float4(acc[r][4], acc[r][5], acc[r][6], acc[r][7]);
    }
}

// ---------------- zero agg / gsum -------------------------------------------
__global__ void zero_agg_kernel()
{
    int i = blockIdx.x * blockDim.x + threadIdx.x;
    ((float4*)g_agg)[i] = make_float4(0.f, 0.f, 0.f, 0.f);
}
__global__ void zero_gsum_kernel()
{
    int i = blockIdx.x * blockDim.x + threadIdx.x;
    if (i < BG * DD) g_gsum[i] = 0.f;
}

// ---------------- fused edge message kernel ---------------------------------
// Per CTA: 64 edges. z = silu(P[src]+Q[dst]+ef@W1c); out = z@W2 + b2 -> atomic agg[dst]
__global__ void __launch_bounds__(256, 2) msg_kernel(
    const int* __restrict__ ei, const float* __restrict__ W1,
    const float* __restrict__ W2, const float* __restrict__ b2, int l)
{
    extern __shared__ float sm[];
    float* Zst  = sm;                      // [256][68] transposed z tile
    float* W1c  = Zst + 256 * 68;          // [16][256]
    float* W2s  = W1c + 16 * 256;          // [32][128] chunk
    float* efs  = W2s + 32 * DD;           // [64][16]
    int*   sidx = (int*)(efs + 64 * NRBF); // [128] src(0..63), dst(64..127)

    int t = threadIdx.x;
    int e0 = blockIdx.x * 64;

    if (t < 64)        sidx[t] = ei[e0 + t];
    else if (t < 128)  sidx[t] = ei[EE + e0 + (t - 64)];
    for (int i = t; i < 64 * NRBF; i += 256) efs[i] = g_ef[(size_t)e0 * NRBF + i];
    const float* w1c_g = W1 + ((size_t)l * 272 + 256) * HH;
    for (int i = t; i < 16 * HH; i += 256) W1c[i] = w1c_g[i];
    __syncthreads();

    // Phase A: build silu'ed z tile (transposed [k][edge])
    int eq = t >> 6;            // 0..3
    int k0 = (t & 63) << 2;     // 0..252 step 4
    for (int eb = 0; eb < 64; eb += 4) {
        int e = eb + eq;
        int s  = sidx[e];
        int dd = sidx[64 + e];
        float4 z = *(const float4*)(g_P + (size_t)s * HH + k0);
        float4 q = *(const float4*)(g_Q + (size_t)dd * HH + k0);
        z.x += q.x; z.y += q.y; z.z += q.z; z.w += q.w;
        #pragma unroll
        for (int j = 0; j < NRBF; j++) {
            float ev = efs[e * NRBF + j];
            float4 w = *(const float4*)(W1c + j * HH + k0);
            z.x += ev * w.x; z.y += ev * w.y; z.z += ev * w.z; z.w += ev * w.w;
        }
        Zst[(k0 + 0) * 68 + e] = silu_f(z.x);
        Zst[(k0 + 1) * 68 + e] = silu_f(z.y);
        Zst[(k0 + 2) * 68 + e] = silu_f(z.z);
        Zst[(k0 + 3) * 68 + e] = silu_f(z.w);
    }

    // Phase B: out[64][128] = Z[64][256] @ W2[256][128]
    int eg = t >> 4;   // 0..15 -> edges eg*4..+3
    int cg = t & 15;   // cols cg*8..+7
    float acc[4][8];
    #pragma unroll
    for (int r = 0; r < 4; r++)
        #pragma unroll
        for (int c = 0; c < 8; c++) acc[r][c] = 0.f;
    const float* w2g = W2 + (size_t)l * HH * DD;
    for (int kc = 0; kc < HH; kc += 32) {
        __syncthreads();
        #pragma unroll
        for (int i = 0; i < 16; i++)
            W2s[t + i * 256] = w2g[(size_t)kc * DD + t + i * 256];
        __syncthreads();
        #pragma unroll
        for (int k = 0; k < 32; k++) {
            float4 zr = *(const float4*)(Zst + (kc + k) * 68 + eg * 4);
            float4 w0 = *(const float4*)(W2s + k * DD + cg * 8);
            float4 w1 = *(const float4*)(W2s + k * DD + cg * 8 + 4);
            float za[4] = {zr.x, zr.y, zr.z, zr.w};
            float wa[8] = {w0.x, w0.y, w0.z, w0.w, w1.x, w1.y, w1.z, w1.w};
            #pragma unroll
            for (int r = 0; r < 4; r++)
                #pragma unroll
                for (int c = 0; c < 8; c++) acc[r][c] += za[r] * wa[c];
        }
    }

    // Phase C: scatter (message bias added per edge)
    int cb = cg * 8;
    float bv[8];
    #pragma unroll
    for (int c = 0; c < 8; c++) bv[c] = b2[l * DD + cb + c];
    #pragma unroll
    for (int r = 0; r < 4; r++) {
        int e  = eg * 4 + r;
        int dd = sidx[64 + e];
        float* ap = g_agg + (size_t)dd * DD + cb;
        #pragma unroll
        for (int c = 0; c < 8; c++) atomicAdd(ap + c, acc[r][c] + bv[c]);
    }
}

// ---------------- per-node update MLP: [h|agg](256) -> 256 -> silu -> 128 ---
__global__ void __launch_bounds__(256) upd_kernel(
    const float* __restrict__ W1, const float* __restrict__ b1,
    const float* __restrict__ W2, const float* __restrict__ b2, int l)
{
    extern __shared__ float sm[];
    float* ins  = sm;               // [32][256]
    float* hidT = sm + 32 * HH;     // [256][36] transposed

    int t = threadIdx.x;
    int n0 = blockIdx.x * 32;
    for (int i = t; i < 32 * DD / 4; i += 256) {
        int node = i / (DD / 4);
        int kq   = i % (DD / 4);
        ((float4*)(ins + node * HH))[kq] =
            ((const float4*)(g_h + (size_t)(n0 + node) * DD))[kq];
        ((float4*)(ins + node * HH + DD))[kq] =
            ((const float4*)(g_agg + (size_t)(n0 + node) * DD))[kq];
    }
    __syncthreads();

    // Phase 1: hid[32][256]
    int ng = t >> 5;    // 0..7 -> nodes ng*4..+3
    int cg = t & 31;    // cols cg*8..+7
    int c0 = cg * 8;
    float acc[4][8];
    #pragma unroll
    for (int c = 0; c < 8; c++) {
        float b = b1[l * HH + c0 + c];
        #pragma unroll
        for (int r = 0; r < 4; r++) acc[r][c] = b;
    }
    const float* w1p = W1 + (size_t)(l * HH) * HH + c0;
    for (int k = 0; k < HH; k++) {
        float a[4];
        #pragma unroll
        for (int r = 0; r < 4; r++) a[r] = ins[(ng * 4 + r) * HH + k];
        float4 w0 = *(const float4*)(w1p + (size_t)k * HH);
        float4 w1v = *(const float4*)(w1p + (size_t)k * HH + 4);
        float wv[8] = {w0.x, w0.y, w0.z, w0.w, w1v.x, w1v.y, w1v.z, w1v.w};
        #pragma unroll
        for (int r = 0; r < 4; r++)
            #pragma unroll
            for (int c = 0; c < 8; c++) acc[r][c] += a[r] * wv[c];
    }
    #pragma unroll
    for (int r = 0; r < 4; r++)
        #pragma unroll
        for (int c = 0; c < 8; c++)
            hidT[(c0 + c) * 36 + ng * 4 + r] = silu_f(acc[r][c]);
    __syncthreads();

    // Phase 2: out[32][128] = hid @ W2 ; h += out + b2
    int ng2 = t >> 5;   // 0..7 -> nodes ng2*4..+3
    int cg2 = t & 31;   // cols cg2*4..+3
    int c2 = cg2 * 4;
    float acc2[4][4];
    #pragma unroll
    for (int r = 0; r < 4; r++)
        #pragma unroll
        for (int c = 0; c < 4; c++) acc2[r][c] = 0.f;
    const float* w2p = W2 + (size_t)(l * HH) * DD + c2;
    for (int k = 0; k < HH; k++) {
        float4 hv = *(const float4*)(hidT + k * 36 + ng2 * 4);
        float4 w  = *(const float4*)(w2p + (size_t)k * DD);
        float ha[4] = {hv.x, hv.y, hv.z, hv.w};
        float wa[4] = {w.x, w.y, w.z, w.w};
        #pragma unroll
        for (int r = 0; r < 4; r++)
            #pragma unroll
            for (int c = 0; c < 4; c++) acc2[r][c] += ha[r] * wa[c];
    }
    #pragma unroll
    for (int r = 0; r < 4; r++) {
        int n = n0 + ng2 * 4 + r;
        #pragma unroll
        for (int c = 0; c < 4; c++)
            g_h[(size_t)n * DD + c2 + c] += acc2[r][c] + b2[l * DD + c2 + c];
    }
}

// ---------------- readout ----------------------------------------------------
__global__ void __launch_bounds__(128) accum_kernel(const int* __restrict__ batch)
{
    int c = threadIdx.x;
    int n0 = blockIdx.x * 64;
    int curb = batch[n0];
    float s = 0.f;
    for (int i = 0; i < 64; i++) {
        int n = n0 + i;
        int b = batch[n];
        if (b != curb) { atomicAdd(&g_gsum[curb * DD + c], s); s = 0.f; curb = b; }
        s += g_h[(size_t)n * DD + c];
    }
    atomicAdd(&g_gsum[curb * DD + c], s);
}

__global__ void __launch_bounds__(256) final_kernel(
    const int* __restrict__ batch,
    const float* __restrict__ rW1, const float* __restrict__ rb1,
    const float* __restrict__ rW2, const float* __restrict__ rb2,
    float* __restrict__ out)
{
    __shared__ int cnt[BG];
    __shared__ float gs[BG * DD];
    __shared__ float hid[BG * HH];
    int t = threadIdx.x;
    if (t < BG) cnt[t] = 0;
    __syncthreads();
    for (int i = t; i < NN; i += 256) atomicAdd(&cnt[batch[i]], 1);
    __syncthreads();
    for (int i = t; i < BG * DD; i += 256) {
        int b = i / DD;
        gs[i] = g_gsum[i] / (float)max(cnt[b], 1);
    }
    __syncthreads();
    // hidden: thread t = column of H
    for (int gr = 0; gr < BG; gr++) {
        float a = rb1[t];
        for (int k = 0; k < DD; k++) a += gs[gr * DD + k] * rW1[k * HH + t];
        hid[gr * HH + t] = silu_f(a);
    }
    __syncthreads();
    for (int idx = t; idx < BG * NOUT; idx += 256) {
        int gr = idx >> 6;
        int c  = idx & 63;
        float a = rb2[c];
        for (int k = 0; k < HH; k++) a += hid[gr * HH + k] * rW2[k * NOUT + c];
        out[idx] = a;
    }
}

// ---------------- launch -----------------------------------------------------
extern "C" void kernel_launch(void* const* d_in, const int* in_sizes, int n_in,
                              void* d_out, int out_size)
{
    const float* pos   = (const float*)d_in[0];
    const float* nf    = (const float*)d_in[1];
    const int*   ei    = (const int*)  d_in[2];
    const int*   batch = (const int*)  d_in[3];
    const float* eW1 = (const float*)d_in[4];
    const float* eb1 = (const float*)d_in[5];
    const float* eW2 = (const float*)d_in[6];
    const float* eb2 = (const float*)d_in[7];
    const float* mW1 = (const float*)d_in[8];
    const float* mb1 = (const float*)d_in[9];
    const float* mW2 = (const float*)d_in[10];
    const float* mb2 = (const float*)d_in[11];
    const float* uW1 = (const float*)d_in[12];
    const float* ub1 = (const float*)d_in[13];
    const float* uW2 = (const float*)d_in[14];
    const float* ub2 = (const float*)d_in[15];
    const float* rW1 = (const float*)d_in[16];
    const float* rb1 = (const float*)d_in[17];
    const float* rW2 = (const float*)d_in[18];
    const float* rb2 = (const float*)d_in[19];
    float* out = (float*)d_out;

    const int MSG_SMEM = (256 * 68 + 16 * 256 + 32 * 128 + 64 * 16) * 4 + 128 * 4;
    const int UPD_SMEM = (32 * 256 + 256 * 36) * 4;
    cudaFuncSetAttribute(msg_kernel, cudaFuncAttributeMaxDynamicSharedMemorySize, MSG_SMEM);
    cudaFuncSetAttribute(upd_kernel, cudaFuncAttributeMaxDynamicSharedMemorySize, UPD_SMEM);

    embed_kernel<<<NN / 4, 128>>>(nf, eW1, eb1, eW2, eb2);
    rbf_kernel<<<EE / 256, 256>>>(pos, ei);

    for (int l = 0; l < NL; l++) {
        pq_kernel<<<NN / 32, 256>>>(mW1, mb1, l);
        zero_agg_kernel<<<NN * DD / 4 / 256, 256>>>();
        msg_kernel<<<EE / 64, 256, MSG_SMEM>>>(ei, mW1, mW2, mb2, l);
        upd_kernel<<<NN / 32, 256, UPD_SMEM>>>(uW1, ub1, uW2, ub2, l);
    }

    zero_gsum_kernel<<<4, 256>>>();
    accum_kernel<<<NN / 64, 128>>>(batch);
    final_kernel<<<1, 256>>>(batch, rW1, rb1, rW2, rb2, out);
}

// round 7
// speedup vs baseline: 1.3148x; 1.3148x over previous
#include <cuda_runtime.h>
#include <cuda_bf16.h>
#include <cstdint>

#define NN 16384
#define EE 524288
#define BG 8
#define FIN 26
#define DD 128
#define HH 256
#define NOUT 64
#define NL 4
#define NRBF 16

// ---------------- device scratch (statically allocated; no cudaMalloc) -------
__device__ float g_h[NN * DD];        // node features (residual stream)
__device__ float g_P[NN * HH];        // h @ W1a + b1
__device__ float g_Q[NN * HH];        // h @ W1b
__device__ float g_ef[EE * NRBF];     // edge RBF features
__device__ float g_agg[NN * DD];      // message aggregation
__device__ float g_gsum[BG * DD];     // per-graph sums
__device__ __nv_bfloat16 g_W2h[NL * HH * DD];   // msg W2 hi bf16
__device__ __nv_bfloat16 g_W2l[NL * HH * DD];   // msg W2 lo bf16 (residual)

__device__ __forceinline__ float silu_f(float x) {
    return x * __frcp_rn(1.f + __expf(-x));
}

// ---------------- mma.sync helpers ------------------------------------------
__device__ __forceinline__ uint32_t smem_u32(const void* p) {
    return (uint32_t)__cvta_generic_to_shared(p);
}
__device__ __forceinline__ void ldsm_x4(uint32_t& r0, uint32_t& r1,
                                        uint32_t& r2, uint32_t& r3, uint32_t a) {
    asm volatile("ldmatrix.sync.aligned.m8n8.x4.shared.b16 {%0,%1,%2,%3}, [%4];"
                 : "=r"(r0), "=r"(r1), "=r"(r2), "=r"(r3) : "r"(a));
}
__device__ __forceinline__ void ldsm_x4_t(uint32_t& r0, uint32_t& r1,
                                          uint32_t& r2, uint32_t& r3, uint32_t a) {
    asm volatile("ldmatrix.sync.aligned.m8n8.x4.trans.shared.b16 {%0,%1,%2,%3}, [%4];"
                 : "=r"(r0), "=r"(r1), "=r"(r2), "=r"(r3) : "r"(a));
}
__device__ __forceinline__ void mma_bf16(float* d, uint32_t a0, uint32_t a1,
                                         uint32_t a2, uint32_t a3,
                                         uint32_t b0, uint32_t b1) {
    asm volatile(
        "mma.sync.aligned.m16n8k16.row.col.f32.bf16.bf16.f32 "
        "{%0,%1,%2,%3}, {%4,%5,%6,%7}, {%8,%9}, {%0,%1,%2,%3};"
        : "+f"(d[0]), "+f"(d[1]), "+f"(d[2]), "+f"(d[3])
        : "r"(a0), "r"(a1), "r"(a2), "r"(a3), "r"(b0), "r"(b1));
}

// ---------------- embedding MLP: 26 -> 128 -> silu -> 128 -------------------
__global__ void __launch_bounds__(128) embed_kernel(
    const float* __restrict__ x, const float* __restrict__ W1,
    const float* __restrict__ b1, const float* __restrict__ W2,
    const float* __restrict__ b2)
{
    __shared__ float xs[4][FIN];
    __shared__ float hid[4][DD];
    int t = threadIdx.x;
    int n0 = blockIdx.x * 4;
    for (int i = t; i < 4 * FIN; i += 128)
        xs[i / FIN][i % FIN] = x[(size_t)n0 * FIN + i];
    __syncthreads();
    float b1t = b1[t];
    #pragma unroll
    for (int nd = 0; nd < 4; nd++) {
        float acc = b1t;
        #pragma unroll
        for (int k = 0; k < FIN; k++) acc += xs[nd][k] * W1[k * DD + t];
        hid[nd][t] = silu_f(acc);
    }
    __syncthreads();
    float b2t = b2[t];
    #pragma unroll
    for (int nd = 0; nd < 4; nd++) {
        float acc = b2t;
        for (int k = 0; k < DD; k++) acc += hid[nd][k] * W2[k * DD + t];
        g_h[(size_t)(n0 + nd) * DD + t] = acc;
    }
}

// ---------------- edge RBF ---------------------------------------------------
__global__ void __launch_bounds__(256) rbf_kernel(
    const float* __restrict__ pos, const int* __restrict__ ei)
{
    int e = blockIdx.x * blockDim.x + threadIdx.x;
    if (e >= EE) return;
    int s  = ei[e];
    int dd = ei[EE + e];
    float dx = pos[dd * 3 + 0] - pos[s * 3 + 0];
    float dy = pos[dd * 3 + 1] - pos[s * 3 + 1];
    float dz = pos[dd * 3 + 2] - pos[s * 3 + 2];
    float d = sqrtf(dx * dx + dy * dy + dz * dz + 1e-12f);
    float env = (d < 10.f) ? 0.5f * (cosf(0.31415926535897932f * d) + 1.f) : 0.f;
    #pragma unroll
    for (int i = 0; i < NRBF; i++) {
        float c = (10.f / 15.f) * (float)i;
        float u = d - c;
        g_ef[(size_t)e * NRBF + i] = env * __expf(-u * u * 1.28f);
    }
}

// ---------------- msg W2 -> bf16 hi/lo split ---------------------------------
__global__ void __launch_bounds__(256) w2bf_kernel(const float* __restrict__ W2)
{
    int i = blockIdx.x * blockDim.x + threadIdx.x;
    if (i < NL * HH * DD) {
        float w = W2[i];
        __nv_bfloat16 wh = __float2bfloat16_rn(w);
        g_W2h[i] = wh;
        g_W2l[i] = __float2bfloat16_rn(w - __bfloat162float(wh));
    }
}

// ---------------- per-layer P/Q node GEMM: [P|Q] = h @ [W1a|W1b] (+b1 on P) --
__global__ void __launch_bounds__(256) pq_kernel(
    const float* __restrict__ W1, const float* __restrict__ b1, int l)
{
    __shared__ float hs[32 * DD];     // 16 KB
    int t = threadIdx.x;
    int n0 = blockIdx.x * 32;
    for (int i = t; i < 32 * DD / 4; i += 256)
        ((float4*)hs)[i] = ((const float4*)(g_h + (size_t)n0 * DD))[i];
    __syncthreads();

    int ng = t >> 6;          // 0..3 -> nodes ng*8..+7
    int cg = t & 63;          // col group -> cols cg*8 (0..511)
    int c0 = cg * 8;
    bool isP = (c0 < HH);
    const float* wp = isP ? (W1 + (size_t)(l * 272) * HH + c0)
                          : (W1 + (size_t)(l * 272 + 128) * HH + (c0 - HH));
    float acc[8][8];
    float bi[8];
    #pragma unroll
    for (int c = 0; c < 8; c++) bi[c] = isP ? b1[l * HH + c0 + c] : 0.f;
    #pragma unroll
    for (int r = 0; r < 8; r++)
        #pragma unroll
        for (int c = 0; c < 8; c++) acc[r][c] = bi[c];

    for (int k = 0; k < DD; k++) {
        float a[8];
        #pragma unroll
        for (int r = 0; r < 8; r++) a[r] = hs[(ng * 8 + r) * DD + k];
        float4 w0 = *(const float4*)(wp + (size_t)k * HH);
        float4 w1 = *(const float4*)(wp + (size_t)k * HH + 4);
        float wv[8] = {w0.x, w0.y, w0.z, w0.w, w1.x, w1.y, w1.z, w1.w};
        #pragma unroll
        for (int r = 0; r < 8; r++)
            #pragma unroll
            for (int c = 0; c < 8; c++) acc[r][c] += a[r] * wv[c];
    }
    #pragma unroll
    for (int r = 0; r < 8; r++) {
        int n = n0 + ng * 8 + r;
        float* dp = isP ? (g_P + (size_t)n * HH + c0)
                        : (g_Q + (size_t)n * HH + (c0 - HH));
        *(float4*)(dp)     = make_float4(acc[r][0], acc[r][1], acc[r][2], acc[r][3]);
        *(float4*)(dp + 4) = make_float4(acc[r][4], acc[r][5], acc[r][6], acc[r][7]);
    }
}

// ---------------- zero agg / gsum -------------------------------------------
__global__ void zero_agg_kernel()
{
    int i = blockIdx.x * blockDim.x + threadIdx.x;
    ((float4*)g_agg)[i] = make_float4(0.f, 0.f, 0.f, 0.f);
}
__global__ void zero_gsum_kernel()
{
    int i = blockIdx.x * blockDim.x + threadIdx.x;
    if (i < BG * DD) g_gsum[i] = 0.f;
}

// ---------------- fused edge message kernel (tensor-core Phase B) -----------
// Per CTA: 64 edges. z = silu(P[src]+Q[dst]+ef@W1c) -> split bf16 (zh, zl);
// out = zh@W2h + zl@W2h + zh@W2l + b2 -> atomic agg[dst]  (Markidis split)
#define ZS_LD 264      // bf16 elems per Zs row (64 rows x 256 k, pad 8)
#define W2_LD 136      // bf16 elems per W2s row (64 k-rows x 128 n, pad 8)

// dynamic smem layout (bytes):
//   [0)                 Zs_h : 64*ZS_LD bf16 = 33792
//   [33792)             Zs_l : 64*ZS_LD bf16 = 33792
//   [67584)  union U:   Phase A: W1c float[16*256] = 16384
//                       Phase B: W2h_s 64*W2_LD bf16 = 17408
//                                W2l_s 64*W2_LD bf16 = 17408  (U size 34816)
//   [102400)            efs  : float[64*16] = 4096
//   [106496)            sidx : int[128]    = 512
//   total 107008 B  (x2 CTAs = 209 KB <= 227 KB)
#define MSG_SMEM_BYTES 107008

__global__ void __launch_bounds__(256, 2) msg_kernel(
    const int* __restrict__ ei, const float* __restrict__ W1,
    const float* __restrict__ b2, int l)
{
    extern __shared__ char smc[];
    __nv_bfloat16* Zs_h = (__nv_bfloat16*)smc;
    __nv_bfloat16* Zs_l = (__nv_bfloat16*)(smc + 33792);
    float*         W1c  = (float*)(smc + 67584);
    __nv_bfloat16* W2hs = (__nv_bfloat16*)(smc + 67584);
    __nv_bfloat16* W2ls = (__nv_bfloat16*)(smc + 67584 + 17408);
    float*         efs  = (float*)(smc + 102400);
    int*           sidx = (int*)(smc + 106496);

    int t = threadIdx.x;
    int e0 = blockIdx.x * 64;

    if (t < 64)        sidx[t] = ei[e0 + t];
    else if (t < 128)  sidx[t] = ei[EE + e0 + (t - 64)];
    for (int i = t; i < 64 * NRBF; i += 256) efs[i] = g_ef[(size_t)e0 * NRBF + i];
    const float* w1c_g = W1 + ((size_t)l * 272 + 256) * HH;
    for (int i = t; i < 16 * HH; i += 256) W1c[i] = w1c_g[i];
    __syncthreads();

    // ---- Phase A: z tile (fp32 math, hi/lo bf16 store), row-major [edge][k]
    {
        int eq = t >> 6;            // 0..3
        int k0 = (t & 63) << 2;     // 0..252 step 4
        for (int eb = 0; eb < 64; eb += 4) {
            int e = eb + eq;
            int s  = sidx[e];
            int dd = sidx[64 + e];
            float4 z = *(const float4*)(g_P + (size_t)s * HH + k0);
            float4 q = *(const float4*)(g_Q + (size_t)dd * HH + k0);
            z.x += q.x; z.y += q.y; z.z += q.z; z.w += q.w;
            #pragma unroll
            for (int j = 0; j < NRBF; j++) {
                float ev = efs[e * NRBF + j];
                float4 w = *(const float4*)(W1c + j * HH + k0);
                z.x += ev * w.x; z.y += ev * w.y; z.z += ev * w.z; z.w += ev * w.w;
            }
            float v[4] = {silu_f(z.x), silu_f(z.y), silu_f(z.z), silu_f(z.w)};
            __nv_bfloat16* zph = Zs_h + e * ZS_LD + k0;
            __nv_bfloat16* zpl = Zs_l + e * ZS_LD + k0;
            #pragma unroll
            for (int j = 0; j < 4; j++) {
                __nv_bfloat16 hv = __float2bfloat16_rn(v[j]);
                zph[j] = hv;
                zpl[j] = __float2bfloat16_rn(v[j] - __bfloat162float(hv));
            }
        }
    }

    // ---- Phase B: out[64][128] = (zh+zl) @ (wh+wl)  (3-term bf16 mma, fp32 acc)
    int warp = t >> 5;
    int lane = t & 31;
    int mw = warp & 3;          // row tile: rows mw*16..+15
    int nw = warp >> 2;         // col tile: cols nw*64..+63

    float acc[8][4];
    #pragma unroll
    for (int n = 0; n < 8; n++)
        #pragma unroll
        for (int c = 0; c < 4; c++) acc[n][c] = 0.f;

    uint32_t a_row   = (uint32_t)(mw * 16 + (lane & 15));
    uint32_t a_khalf = (uint32_t)((lane >> 4) << 3);
    uint32_t zsh_base = smem_u32(Zs_h);
    uint32_t zsl_base = smem_u32(Zs_l);
    uint32_t b_krow = (uint32_t)(lane & 15);
    uint32_t b_noff = (uint32_t)(nw * 64 + ((lane >> 4) << 3));
    uint32_t w2h_base = smem_u32(W2hs);
    uint32_t w2l_base = smem_u32(W2ls);

    const __nv_bfloat16* w2hg = g_W2h + (size_t)l * HH * DD;
    const __nv_bfloat16* w2lg = g_W2l + (size_t)l * HH * DD;

    for (int kc = 0; kc < HH; kc += 64) {
        __syncthreads();
        // stage W2 hi+lo chunk [64][128] -> padded smem
        #pragma unroll
        for (int j = 0; j < 8; j++) {
            int i = t + j * 256;            // uint2 index over 2048
            int kk = i >> 5;                // 0..63
            int n4 = (i & 31) << 2;         // 0..124 step 4
            *(uint2*)(W2hs + kk * W2_LD + n4) =
                *(const uint2*)(w2hg + (size_t)(kc + kk) * DD + n4);
            *(uint2*)(W2ls + kk * W2_LD + n4) =
                *(const uint2*)(w2lg + (size_t)(kc + kk) * DD + n4);
        }
        __syncthreads();

        #pragma unroll
        for (int ks = 0; ks < 4; ks++) {
            int k = kc + ks * 16;
            uint32_t ah0, ah1, ah2, ah3, al0, al1, al2, al3;
            ldsm_x4(ah0, ah1, ah2, ah3,
                    zsh_base + (a_row * ZS_LD + (uint32_t)k + a_khalf) * 2);
            ldsm_x4(al0, al1, al2, al3,
                    zsl_base + (a_row * ZS_LD + (uint32_t)k + a_khalf) * 2);
            #pragma unroll
            for (int np = 0; np < 4; np++) {
                uint32_t off = (((uint32_t)(ks * 16) + b_krow) * W2_LD
                                + b_noff + (uint32_t)(np * 16)) * 2;
                uint32_t bh0, bh1, bh2, bh3, bl0, bl1, bl2, bl3;
                ldsm_x4_t(bh0, bh1, bh2, bh3, w2h_base + off);
                ldsm_x4_t(bl0, bl1, bl2, bl3, w2l_base + off);
                float* a0 = acc[np * 2 + 0];
                float* a1 = acc[np * 2 + 1];
                mma_bf16(a0, ah0, ah1, ah2, ah3, bh0, bh1);
                mma_bf16(a0, al0, al1, al2, al3, bh0, bh1);
                mma_bf16(a0, ah0, ah1, ah2, ah3, bl0, bl1);
                mma_bf16(a1, ah0, ah1, ah2, ah3, bh2, bh3);
                mma_bf16(a1, al0, al1, al2, al3, bh2, bh3);
                mma_bf16(a1, ah0, ah1, ah2, ah3, bl2, bl3);
            }
        }
    }

    // ---- Phase C: scatter with per-edge bias
    int r0 = mw * 16 + (lane >> 2);
    int r1 = r0 + 8;
    int dst0 = sidx[64 + r0];
    int dst1 = sidx[64 + r1];
    #pragma unroll
    for (int n = 0; n < 8; n++) {
        int c0 = nw * 64 + n * 8 + (lane & 3) * 2;
        float bva = b2[l * DD + c0];
        float bvb = b2[l * DD + c0 + 1];
        float* p0 = g_agg + (size_t)dst0 * DD + c0;
        float* p1 = g_agg + (size_t)dst1 * DD + c0;
        atomicAdd(p0,     acc[n][0] + bva);
        atomicAdd(p0 + 1, acc[n][1] + bvb);
        atomicAdd(p1,     acc[n][2] + bva);
        atomicAdd(p1 + 1, acc[n][3] + bvb);
    }
}

// ---------------- per-node update MLP: [h|agg](256) -> 256 -> silu -> 128 ---
__global__ void __launch_bounds__(256) upd_kernel(
    const float* __restrict__ W1, const float* __restrict__ b1,
    const float* __restrict__ W2, const float* __restrict__ b2, int l)
{
    extern __shared__ float sm[];
    float* ins  = sm;               // [32][256]
    float* hidT = sm + 32 * HH;     // [256][36] transposed

    int t = threadIdx.x;
    int n0 = blockIdx.x * 32;
    for (int i = t; i < 32 * DD / 4; i += 256) {
        int node = i / (DD / 4);
        int kq   = i % (DD / 4);
        ((float4*)(ins + node * HH))[kq] =
            ((const float4*)(g_h + (size_t)(n0 + node) * DD))[kq];
        ((float4*)(ins + node * HH + DD))[kq] =
            ((const float4*)(g_agg + (size_t)(n0 + node) * DD))[kq];
    }
    __syncthreads();

    int ng = t >> 5;
    int cg = t & 31;
    int c0 = cg * 8;
    float acc[4][8];
    #pragma unroll
    for (int c = 0; c < 8; c++) {
        float b = b1[l * HH + c0 + c];
        #pragma unroll
        for (int r = 0; r < 4; r++) acc[r][c] = b;
    }
    const float* w1p = W1 + (size_t)(l * HH) * HH + c0;
    for (int k = 0; k < HH; k++) {
        float a[4];
        #pragma unroll
        for (int r = 0; r < 4; r++) a[r] = ins[(ng * 4 + r) * HH + k];
        float4 w0 = *(const float4*)(w1p + (size_t)k * HH);
        float4 w1v = *(const float4*)(w1p + (size_t)k * HH + 4);
        float wv[8] = {w0.x, w0.y, w0.z, w0.w, w1v.x, w1v.y, w1v.z, w1v.w};
        #pragma unroll
        for (int r = 0; r < 4; r++)
            #pragma unroll
            for (int c = 0; c < 8; c++) acc[r][c] += a[r] * wv[c];
    }
    #pragma unroll
    for (int r = 0; r < 4; r++)
        #pragma unroll
        for (int c = 0; c < 8; c++)
            hidT[(c0 + c) * 36 + ng * 4 + r] = silu_f(acc[r][c]);
    __syncthreads();

    int ng2 = t >> 5;
    int cg2 = t & 31;
    int c2 = cg2 * 4;
    float acc2[4][4];
    #pragma unroll
    for (int r = 0; r < 4; r++)
        #pragma unroll
        for (int c = 0; c < 4; c++) acc2[r][c] = 0.f;
    const float* w2p = W2 + (size_t)(l * HH) * DD + c2;
    for (int k = 0; k < HH; k++) {
        float4 hv = *(const float4*)(hidT + k * 36 + ng2 * 4);
        float4 w  = *(const float4*)(w2p + (size_t)k * DD);
        float ha[4] = {hv.x, hv.y, hv.z, hv.w};
        float wa[4] = {w.x, w.y, w.z, w.w};
        #pragma unroll
        for (int r = 0; r < 4; r++)
            #pragma unroll
            for (int c = 0; c < 4; c++) acc2[r][c] += ha[r] * wa[c];
    }
    #pragma unroll
    for (int r = 0; r < 4; r++) {
        int n = n0 + ng2 * 4 + r;
        #pragma unroll
        for (int c = 0; c < 4; c++)
            g_h[(size_t)n * DD + c2 + c] += acc2[r][c] + b2[l * DD + c2 + c];
    }
}

// ---------------- readout ----------------------------------------------------
__global__ void __launch_bounds__(128) accum_kernel(const int* __restrict__ batch)
{
    int c = threadIdx.x;
    int n0 = blockIdx.x * 64;
    int curb = batch[n0];
    float s = 0.f;
    for (int i = 0; i < 64; i++) {
        int n = n0 + i;
        int b = batch[n];
        if (b != curb) { atomicAdd(&g_gsum[curb * DD + c], s); s = 0.f; curb = b; }
        s += g_h[(size_t)n * DD + c];
    }
    atomicAdd(&g_gsum[curb * DD + c], s);
}

__global__ void __launch_bounds__(256) final_kernel(
    const int* __restrict__ batch,
    const float* __restrict__ rW1, const float* __restrict__ rb1,
    const float* __restrict__ rW2, const float* __restrict__ rb2,
    float* __restrict__ out)
{
    __shared__ int cnt[BG];
    __shared__ float gs[BG * DD];
    __shared__ float hid[BG * HH];
    int t = threadIdx.x;
    if (t < BG) cnt[t] = 0;
    __syncthreads();
    for (int i = t; i < NN; i += 256) atomicAdd(&cnt[batch[i]], 1);
    __syncthreads();
    for (int i = t; i < BG * DD; i += 256) {
        int b = i / DD;
        gs[i] = g_gsum[i] / (float)max(cnt[b], 1);
    }
    __syncthreads();
    for (int gr = 0; gr < BG; gr++) {
        float a = rb1[t];
        for (int k = 0; k < DD; k++) a += gs[gr * DD + k] * rW1[k * HH + t];
        hid[gr * HH + t] = silu_f(a);
    }
    __syncthreads();
    for (int idx = t; idx < BG * NOUT; idx += 256) {
        int gr = idx >> 6;
        int c  = idx & 63;
        float a = rb2[c];
        for (int k = 0; k < HH; k++) a += hid[gr * HH + k] * rW2[k * NOUT + c];
        out[idx] = a;
    }
}

// ---------------- launch -----------------------------------------------------
extern "C" void kernel_launch(void* const* d_in, const int* in_sizes, int n_in,
                              void* d_out, int out_size)
{
    const float* pos   = (const float*)d_in[0];
    const float* nf    = (const float*)d_in[1];
    const int*   ei    = (const int*)  d_in[2];
    const int*   batch = (const int*)  d_in[3];
    const float* eW1 = (const float*)d_in[4];
    const float* eb1 = (const float*)d_in[5];
    const float* eW2 = (const float*)d_in[6];
    const float* eb2 = (const float*)d_in[7];
    const float* mW1 = (const float*)d_in[8];
    const float* mb1 = (const float*)d_in[9];
    const float* mW2 = (const float*)d_in[10];
    const float* mb2 = (const float*)d_in[11];
    const float* uW1 = (const float*)d_in[12];
    const float* ub1 = (const float*)d_in[13];
    const float* uW2 = (const float*)d_in[14];
    const float* ub2 = (const float*)d_in[15];
    const float* rW1 = (const float*)d_in[16];
    const float* rb1 = (const float*)d_in[17];
    const float* rW2 = (const float*)d_in[18];
    const float* rb2 = (const float*)d_in[19];
    float* out = (float*)d_out;

    const int UPD_SMEM = (32 * HH + 256 * 36) * 4;
    cudaFuncSetAttribute(msg_kernel, cudaFuncAttributeMaxDynamicSharedMemorySize,
                         MSG_SMEM_BYTES);
    cudaFuncSetAttribute(upd_kernel, cudaFuncAttributeMaxDynamicSharedMemorySize,
                         UPD_SMEM);

    embed_kernel<<<NN / 4, 128>>>(nf, eW1, eb1, eW2, eb2);
    rbf_kernel<<<EE / 256, 256>>>(pos, ei);
    w2bf_kernel<<<(NL * HH * DD + 255) / 256, 256>>>(mW2);

    for (int l = 0; l < NL; l++) {
        pq_kernel<<<NN / 32, 256>>>(mW1, mb1, l);
        zero_agg_kernel<<<NN * DD / 4 / 256, 256>>>();
        msg_kernel<<<EE / 64, 256, MSG_SMEM_BYTES>>>(ei, mW1, mb2, l);
        upd_kernel<<<NN / 32, 256, UPD_SMEM>>>(uW1, ub1, uW2, ub2, l);
    }

    zero_gsum_kernel<<<4, 256>>>();
    accum_kernel<<<NN / 64, 128>>>(batch);
    final_kernel<<<1, 256>>>(batch, rW1, rb1, rW2, rb2, out);
}

// round 8
// speedup vs baseline: 3.1223x; 2.3747x over previous
#include <cuda_runtime.h>
#include <cuda_bf16.h>
#include <cstdint>

#define NN 16384
#define EE 524288
#define BG 8
#define FIN 26
#define DD 128
#define HH 256
#define NOUT 64
#define NL 4
#define NRBF 16

// ---------------- device scratch (statically allocated; no cudaMalloc) -------
__device__ float g_h[NN * DD];        // node features (residual stream)
__device__ float g_P[NN * HH];        // h @ W1a + b1
__device__ float g_Q[NN * HH];        // h @ W1b
__device__ float g_ef[EE * NRBF];     // edge RBF features
__device__ float g_S[NN * HH];        // sum of silu(z) per dst node
__device__ float g_agg[NN * DD];      // message aggregation (= S@W2 + deg*b2)
__device__ float g_degf[NN];          // per-node in-degree (float)
__device__ float g_gsum[BG * DD];     // per-graph sums

__device__ __forceinline__ float silu_f(float x) {
    return x * __frcp_rn(1.f + __expf(-x));
}

__device__ __forceinline__ void red_v4(float* p, float a, float b, float c, float d) {
    asm volatile("red.global.add.v4.f32 [%0], {%1,%2,%3,%4};"
                 :: "l"(p), "f"(a), "f"(b), "f"(c), "f"(d) : "memory");
}

// ---------------- embedding MLP: 26 -> 128 -> silu -> 128 -------------------
__global__ void __launch_bounds__(128) embed_kernel(
    const float* __restrict__ x, const float* __restrict__ W1,
    const float* __restrict__ b1, const float* __restrict__ W2,
    const float* __restrict__ b2)
{
    __shared__ float xs[4][FIN];
    __shared__ float hid[4][DD];
    int t = threadIdx.x;
    int n0 = blockIdx.x * 4;
    for (int i = t; i < 4 * FIN; i += 128)
        xs[i / FIN][i % FIN] = x[(size_t)n0 * FIN + i];
    __syncthreads();
    float b1t = b1[t];
    #pragma unroll
    for (int nd = 0; nd < 4; nd++) {
        float acc = b1t;
        #pragma unroll
        for (int k = 0; k < FIN; k++) acc += xs[nd][k] * W1[k * DD + t];
        hid[nd][t] = silu_f(acc);
    }
    __syncthreads();
    float b2t = b2[t];
    #pragma unroll
    for (int nd = 0; nd < 4; nd++) {
        float acc = b2t;
        for (int k = 0; k < DD; k++) acc += hid[nd][k] * W2[k * DD + t];
        g_h[(size_t)(n0 + nd) * DD + t] = acc;
    }
}

// ---------------- edge RBF ---------------------------------------------------
__global__ void __launch_bounds__(256) rbf_kernel(
    const float* __restrict__ pos, const int* __restrict__ ei)
{
    int e = blockIdx.x * blockDim.x + threadIdx.x;
    if (e >= EE) return;
    int s  = ei[e];
    int dd = ei[EE + e];
    float dx = pos[dd * 3 + 0] - pos[s * 3 + 0];
    float dy = pos[dd * 3 + 1] - pos[s * 3 + 1];
    float dz = pos[dd * 3 + 2] - pos[s * 3 + 2];
    float d = sqrtf(dx * dx + dy * dy + dz * dz + 1e-12f);
    float env = (d < 10.f) ? 0.5f * (cosf(0.31415926535897932f * d) + 1.f) : 0.f;
    #pragma unroll
    for (int i = 0; i < NRBF; i++) {
        float c = (10.f / 15.f) * (float)i;
        float u = d - c;
        g_ef[(size_t)e * NRBF + i] = env * __expf(-u * u * 1.28f);
    }
}

// ---------------- degree count (once per launch) -----------------------------
__global__ void __launch_bounds__(256) zero_deg_kernel()
{
    int i = blockIdx.x * blockDim.x + threadIdx.x;
    if (i < NN) g_degf[i] = 0.f;
}
__global__ void __launch_bounds__(256) deg_kernel(const int* __restrict__ ei)
{
    int e = blockIdx.x * blockDim.x + threadIdx.x;
    if (e < EE) atomicAdd(&g_degf[ei[EE + e]], 1.f);
}

// ---------------- per-layer P/Q node GEMM: [P|Q] = h @ [W1a|W1b] (+b1 on P) --
__global__ void __launch_bounds__(256) pq_kernel(
    const float* __restrict__ W1, const float* __restrict__ b1, int l)
{
    __shared__ float hs[32 * DD];     // 16 KB
    int t = threadIdx.x;
    int n0 = blockIdx.x * 32;
    for (int i = t; i < 32 * DD / 4; i += 256)
        ((float4*)hs)[i] = ((const float4*)(g_h + (size_t)n0 * DD))[i];
    __syncthreads();

    int ng = t >> 6;          // 0..3 -> nodes ng*8..+7
    int cg = t & 63;          // col group -> cols cg*8 (0..511)
    int c0 = cg * 8;
    bool isP = (c0 < HH);
    const float* wp = isP ? (W1 + (size_t)(l * 272) * HH + c0)
                          : (W1 + (size_t)(l * 272 + 128) * HH + (c0 - HH));
    float acc[8][8];
    float bi[8];
    #pragma unroll
    for (int c = 0; c < 8; c++) bi[c] = isP ? b1[l * HH + c0 + c] : 0.f;
    #pragma unroll
    for (int r = 0; r < 8; r++)
        #pragma unroll
        for (int c = 0; c < 8; c++) acc[r][c] = bi[c];

    for (int k = 0; k < DD; k++) {
        float a[8];
        #pragma unroll
        for (int r = 0; r < 8; r++) a[r] = hs[(ng * 8 + r) * DD + k];
        float4 w0 = *(const float4*)(wp + (size_t)k * HH);
        float4 w1 = *(const float4*)(wp + (size_t)k * HH + 4);
        float wv[8] = {w0.x, w0.y, w0.z, w0.w, w1.x, w1.y, w1.z, w1.w};
        #pragma unroll
        for (int r = 0; r < 8; r++)
            #pragma unroll
            for (int c = 0; c < 8; c++) acc[r][c] += a[r] * wv[c];
    }
    #pragma unroll
    for (int r = 0; r < 8; r++) {
        int n = n0 + ng * 8 + r;
        float* dp = isP ? (g_P + (size_t)n * HH + c0)
                        : (g_Q + (size_t)n * HH + (c0 - HH));
        *(float4*)(dp)     = make_float4(acc[r][0], acc[r][1], acc[r][2], acc[r][3]);
        *(float4*)(dp + 4) = make_float4(acc[r][4], acc[r][5], acc[r][6], acc[r][7]);
    }
}

// ---------------- zero S ------------------------------------------------------
__global__ void zero_S_kernel()
{
    int i = blockIdx.x * blockDim.x + threadIdx.x;
    ((float4*)g_S)[i] = make_float4(0.f, 0.f, 0.f, 0.f);
}
__global__ void zero_gsum_kernel()
{
    int i = blockIdx.x * blockDim.x + threadIdx.x;
    if (i < BG * DD) g_gsum[i] = 0.f;
}

// ---------------- edge kernel: S[dst] += silu(P[src]+Q[dst]+ef@W1c) ----------
#define EPC 128   // edges per CTA

__global__ void __launch_bounds__(256) edge_kernel(
    const int* __restrict__ ei, const float* __restrict__ W1, int l)
{
    __shared__ float W1c[16 * HH];      // 16 KB
    __shared__ float efs[EPC * NRBF];   // 8 KB
    __shared__ int   sidx[2 * EPC];     // 1 KB

    int t = threadIdx.x;
    int e0 = blockIdx.x * EPC;

    if (t < EPC)            sidx[t] = ei[e0 + t];
    else if (t < 2 * EPC)   sidx[t] = ei[EE + e0 + (t - EPC)];
    for (int i = t; i < EPC * NRBF; i += 256) efs[i] = g_ef[(size_t)e0 * NRBF + i];
    const float* w1c_g = W1 + ((size_t)l * 272 + 256) * HH;
    for (int i = t; i < 16 * HH; i += 256) W1c[i] = w1c_g[i];
    __syncthreads();

    int eq = t >> 6;            // 0..3 (4 edges in flight)
    int k0 = (t & 63) << 2;     // 0..252 step 4

    for (int eb = 0; eb < EPC; eb += 4) {
        int e = eb + eq;
        int s  = sidx[e];
        int dd = sidx[EPC + e];
        float4 z = *(const float4*)(g_P + (size_t)s * HH + k0);
        float4 q = *(const float4*)(g_Q + (size_t)dd * HH + k0);
        z.x += q.x; z.y += q.y; z.z += q.z; z.w += q.w;
        #pragma unroll
        for (int j = 0; j < NRBF; j++) {
            float ev = efs[e * NRBF + j];
            float4 w = *(const float4*)(W1c + j * HH + k0);
            z.x += ev * w.x; z.y += ev * w.y; z.z += ev * w.z; z.w += ev * w.w;
        }
        red_v4(g_S + (size_t)dd * HH + k0,
               silu_f(z.x), silu_f(z.y), silu_f(z.z), silu_f(z.w));
    }
}

// ---------------- agg = S @ W2 + deg * b2  (N x 256 x 128) -------------------
__global__ void __launch_bounds__(256) agg_kernel(
    const float* __restrict__ W2, const float* __restrict__ b2, int l)
{
    __shared__ float Ss[32 * HH];   // 32 KB
    int t = threadIdx.x;
    int n0 = blockIdx.x * 32;
    for (int i = t; i < 32 * HH / 4; i += 256)
        ((float4*)Ss)[i] = ((const float4*)(g_S + (size_t)n0 * HH))[i];
    __syncthreads();

    int ng = t >> 5;     // 0..7 -> nodes ng*4..+3
    int cg = t & 31;     // cols cg*4..+3
    int c0 = cg * 4;
    float bv[4];
    #pragma unroll
    for (int c = 0; c < 4; c++) bv[c] = b2[l * DD + c0 + c];

    float acc[4][4];
    #pragma unroll
    for (int r = 0; r < 4; r++) {
        float dg = g_degf[n0 + ng * 4 + r];
        #pragma unroll
        for (int c = 0; c < 4; c++) acc[r][c] = dg * bv[c];
    }

    const float* w2p = W2 + (size_t)l * HH * DD + c0;
    for (int k = 0; k < HH; k++) {
        float4 w = *(const float4*)(w2p + (size_t)k * DD);
        float a[4];
        #pragma unroll
        for (int r = 0; r < 4; r++) a[r] = Ss[(ng * 4 + r) * HH + k];
        float wa[4] = {w.x, w.y, w.z, w.w};
        #pragma unroll
        for (int r = 0; r < 4; r++)
            #pragma unroll
            for (int c = 0; c < 4; c++) acc[r][c] += a[r] * wa[c];
    }
    #pragma unroll
    for (int r = 0; r < 4; r++) {
        int n = n0 + ng * 4 + r;
        *(float4*)(g_agg + (size_t)n * DD + c0) =
            make_float4(acc[r][0], acc[r][1], acc[r][2], acc[r][3]);
    }
}

// ---------------- per-node update MLP: [h|agg](256) -> 256 -> silu -> 128 ---
__global__ void __launch_bounds__(256) upd_kernel(
    const float* __restrict__ W1, const float* __restrict__ b1,
    const float* __restrict__ W2, const float* __restrict__ b2, int l)
{
    extern __shared__ float sm[];
    float* ins  = sm;               // [32][256]
    float* hidT = sm + 32 * HH;     // [256][36] transposed

    int t = threadIdx.x;
    int n0 = blockIdx.x * 32;
    for (int i = t; i < 32 * DD / 4; i += 256) {
        int node = i / (DD / 4);
        int kq   = i % (DD / 4);
        ((float4*)(ins + node * HH))[kq] =
            ((const float4*)(g_h + (size_t)(n0 + node) * DD))[kq];
        ((float4*)(ins + node * HH + DD))[kq] =
            ((const float4*)(g_agg + (size_t)(n0 + node) * DD))[kq];
    }
    __syncthreads();

    int ng = t >> 5;
    int cg = t & 31;
    int c0 = cg * 8;
    float acc[4][8];
    #pragma unroll
    for (int c = 0; c < 8; c++) {
        float b = b1[l * HH + c0 + c];
        #pragma unroll
        for (int r = 0; r < 4; r++) acc[r][c] = b;
    }
    const float* w1p = W1 + (size_t)(l * HH) * HH + c0;
    for (int k = 0; k < HH; k++) {
        float a[4];
        #pragma unroll
        for (int r = 0; r < 4; r++) a[r] = ins[(ng * 4 + r) * HH + k];
        float4 w0 = *(const float4*)(w1p + (size_t)k * HH);
        float4 w1v = *(const float4*)(w1p + (size_t)k * HH + 4);
        float wv[8] = {w0.x, w0.y, w0.z, w0.w, w1v.x, w1v.y, w1v.z, w1v.w};
        #pragma unroll
        for (int r = 0; r < 4; r++)
            #pragma unroll
            for (int c = 0; c < 8; c++) acc[r][c] += a[r] * wv[c];
    }
    #pragma unroll
    for (int r = 0; r < 4; r++)
        #pragma unroll
        for (int c = 0; c < 8; c++)
            hidT[(c0 + c) * 36 + ng * 4 + r] = silu_f(acc[r][c]);
    __syncthreads();

    int ng2 = t >> 5;
    int cg2 = t & 31;
    int c2 = cg2 * 4;
    float acc2[4][4];
    #pragma unroll
    for (int r = 0; r < 4; r++)
        #pragma unroll
        for (int c = 0; c < 4; c++) acc2[r][c] = 0.f;
    const float* w2p = W2 + (size_t)(l * HH) * DD + c2;
    for (int k = 0; k < HH; k++) {
        float4 hv = *(const float4*)(hidT + k * 36 + ng2 * 4);
        float4 w  = *(const float4*)(w2p + (size_t)k * DD);
        float ha[4] = {hv.x, hv.y, hv.z, hv.w};
        float wa[4] = {w.x, w.y, w.z, w.w};
        #pragma unroll
        for (int r = 0; r < 4; r++)
            #pragma unroll
            for (int c = 0; c < 4; c++) acc2[r][c] += ha[r] * wa[c];
    }
    #pragma unroll
    for (int r = 0; r < 4; r++) {
        int n = n0 + ng2 * 4 + r;
        #pragma unroll
        for (int c = 0; c < 4; c++)
            g_h[(size_t)n * DD + c2 + c] += acc2[r][c] + b2[l * DD + c2 + c];
    }
}

// ---------------- readout ----------------------------------------------------
__global__ void __launch_bounds__(128) accum_kernel(const int* __restrict__ batch)
{
    int c = threadIdx.x;
    int n0 = blockIdx.x * 64;
    int curb = batch[n0];
    float s = 0.f;
    for (int i = 0; i < 64; i++) {
        int n = n0 + i;
        int b = batch[n];
        if (b != curb) { atomicAdd(&g_gsum[curb * DD + c], s); s = 0.f; curb = b; }
        s += g_h[(size_t)n * DD + c];
    }
    atomicAdd(&g_gsum[curb * DD + c], s);
}

__global__ void __launch_bounds__(256) final_kernel(
    const int* __restrict__ batch,
    const float* __restrict__ rW1, const float* __restrict__ rb1,
    const float* __restrict__ rW2, const float* __restrict__ rb2,
    float* __restrict__ out)
{
    __shared__ int cnt[BG];
    __shared__ float gs[BG * DD];
    __shared__ float hid[BG * HH];
    int t = threadIdx.x;
    if (t < BG) cnt[t] = 0;
    __syncthreads();
    for (int i = t; i < NN; i += 256) atomicAdd(&cnt[batch[i]], 1);
    __syncthreads();
    for (int i = t; i < BG * DD; i += 256) {
        int b = i / DD;
        gs[i] = g_gsum[i] / (float)max(cnt[b], 1);
    }
    __syncthreads();
    for (int gr = 0; gr < BG; gr++) {
        float a = rb1[t];
        for (int k = 0; k < DD; k++) a += gs[gr * DD + k] * rW1[k * HH + t];
        hid[gr * HH + t] = silu_f(a);
    }
    __syncthreads();
    for (int idx = t; idx < BG * NOUT; idx += 256) {
        int gr = idx >> 6;
        int c  = idx & 63;
        float a = rb2[c];
        for (int k = 0; k < HH; k++) a += hid[gr * HH + k] * rW2[k * NOUT + c];
        out[idx] = a;
    }
}

// ---------------- launch -----------------------------------------------------
extern "C" void kernel_launch(void* const* d_in, const int* in_sizes, int n_in,
                              void* d_out, int out_size)
{
    const float* pos   = (const float*)d_in[0];
    const float* nf    = (const float*)d_in[1];
    const int*   ei    = (const int*)  d_in[2];
    const int*   batch = (const int*)  d_in[3];
    const float* eW1 = (const float*)d_in[4];
    const float* eb1 = (const float*)d_in[5];
    const float* eW2 = (const float*)d_in[6];
    const float* eb2 = (const float*)d_in[7];
    const float* mW1 = (const float*)d_in[8];
    const float* mb1 = (const float*)d_in[9];
    const float* mW2 = (const float*)d_in[10];
    const float* mb2 = (const float*)d_in[11];
    const float* uW1 = (const float*)d_in[12];
    const float* ub1 = (const float*)d_in[13];
    const float* uW2 = (const float*)d_in[14];
    const float* ub2 = (const float*)d_in[15];
    const float* rW1 = (const float*)d_in[16];
    const float* rb1 = (const float*)d_in[17];
    const float* rW2 = (const float*)d_in[18];
    const float* rb2 = (const float*)d_in[19];
    float* out = (float*)d_out;

    const int UPD_SMEM = (32 * HH + 256 * 36) * 4;
    cudaFuncSetAttribute(upd_kernel, cudaFuncAttributeMaxDynamicSharedMemorySize,
                         UPD_SMEM);

    embed_kernel<<<NN / 4, 128>>>(nf, eW1, eb1, eW2, eb2);
    rbf_kernel<<<EE / 256, 256>>>(pos, ei);
    zero_deg_kernel<<<NN / 256, 256>>>();
    deg_kernel<<<EE / 256, 256>>>(ei);

    for (int l = 0; l < NL; l++) {
        pq_kernel<<<NN / 32, 256>>>(mW1, mb1, l);
        zero_S_kernel<<<NN * HH / 4 / 256, 256>>>();
        edge_kernel<<<EE / EPC, 256>>>(ei, mW1, l);
        agg_kernel<<<NN / 32, 256>>>(mW2, mb2, l);
        upd_kernel<<<NN / 32, 256, UPD_SMEM>>>(uW1, ub1, uW2, ub2, l);
    }

    zero_gsum_kernel<<<4, 256>>>();
    accum_kernel<<<NN / 64, 128>>>(batch);
    final_kernel<<<1, 256>>>(batch, rW1, rb1, rW2, rb2, out);
}

// round 9
// speedup vs baseline: 4.0903x; 1.3100x over previous
#include <cuda_runtime.h>
#include <cuda_bf16.h>
#include <cstdint>

#define NN 16384
#define EE 524288
#define BG 8
#define FIN 26
#define DD 128
#define HH 256
#define NOUT 64
#define NL 4
#define NRBF 16

// ---------------- device scratch (statically allocated; no cudaMalloc) -------
__device__ float g_h[NN * DD];        // node features (residual stream)
__device__ float g_P[NN * HH];        // h @ W1a + b1
__device__ float g_Q[NN * HH];        // h @ W1b
__device__ float g_ef[EE * NRBF];     // edge RBF features
__device__ float g_S[NN * HH];        // sum of silu(z) per dst node
__device__ float g_agg[NN * DD];      // message aggregation (= S@W2 + deg*b2)
__device__ float g_degf[NN];          // per-node in-degree (float)
__device__ float g_gsum[BG * DD];     // per-graph sums
// pre-split bf16 weights (hi/lo Markidis pairs)
__device__ __nv_bfloat16 g_Wpq_h[NL * 128 * 512];  // [W1a|W1b] concat on N
__device__ __nv_bfloat16 g_Wpq_l[NL * 128 * 512];
__device__ __nv_bfloat16 g_uW1h[NL * HH * HH];
__device__ __nv_bfloat16 g_uW1l[NL * HH * HH];
__device__ __nv_bfloat16 g_uW2h[NL * HH * DD];
__device__ __nv_bfloat16 g_uW2l[NL * HH * DD];

__device__ __forceinline__ float silu_f(float x) {
    return x * __frcp_rn(1.f + __expf(-x));
}

__device__ __forceinline__ void red_v4(float* p, float a, float b, float c, float d) {
    asm volatile("red.global.add.v4.f32 [%0], {%1,%2,%3,%4};"
                 :: "l"(p), "f"(a), "f"(b), "f"(c), "f"(d) : "memory");
}

// ---------------- mma.sync helpers ------------------------------------------
__device__ __forceinline__ uint32_t smem_u32(const void* p) {
    return (uint32_t)__cvta_generic_to_shared(p);
}
__device__ __forceinline__ void ldsm_x4(uint32_t& r0, uint32_t& r1,
                                        uint32_t& r2, uint32_t& r3, uint32_t a) {
    asm volatile("ldmatrix.sync.aligned.m8n8.x4.shared.b16 {%0,%1,%2,%3}, [%4];"
                 : "=r"(r0), "=r"(r1), "=r"(r2), "=r"(r3) : "r"(a));
}
__device__ __forceinline__ void ldsm_x4_t(uint32_t& r0, uint32_t& r1,
                                          uint32_t& r2, uint32_t& r3, uint32_t a) {
    asm volatile("ldmatrix.sync.aligned.m8n8.x4.trans.shared.b16 {%0,%1,%2,%3}, [%4];"
                 : "=r"(r0), "=r"(r1), "=r"(r2), "=r"(r3) : "r"(a));
}
__device__ __forceinline__ void mma_bf16(float* d, uint32_t a0, uint32_t a1,
                                         uint32_t a2, uint32_t a3,
                                         uint32_t b0, uint32_t b1) {
    asm volatile(
        "mma.sync.aligned.m16n8k16.row.col.f32.bf16.bf16.f32 "
        "{%0,%1,%2,%3}, {%4,%5,%6,%7}, {%8,%9}, {%0,%1,%2,%3};"
        : "+f"(d[0]), "+f"(d[1]), "+f"(d[2]), "+f"(d[3])
        : "r"(a0), "r"(a1), "r"(a2), "r"(a3), "r"(b0), "r"(b1));
}
// pack two floats into (hi-u32, lo-u32) bf16x2 Markidis pairs
__device__ __forceinline__ void split2(float f0, float f1, uint32_t& hi, uint32_t& lo) {
    __nv_bfloat16 h0 = __float2bfloat16_rn(f0);
    __nv_bfloat16 h1 = __float2bfloat16_rn(f1);
    __nv_bfloat16 l0 = __float2bfloat16_rn(f0 - __bfloat162float(h0));
    __nv_bfloat16 l1 = __float2bfloat16_rn(f1 - __bfloat162float(h1));
    hi = (uint32_t)__bfloat16_as_ushort(h0) | ((uint32_t)__bfloat16_as_ushort(h1) << 16);
    lo = (uint32_t)__bfloat16_as_ushort(l0) | ((uint32_t)__bfloat16_as_ushort(l1) << 16);
}

// ---------------- weight pre-split kernels -----------------------------------
__global__ void __launch_bounds__(256) split_wpq_kernel(const float* __restrict__ mW1)
{
    int i = blockIdx.x * blockDim.x + threadIdx.x;
    if (i >= NL * 128 * 512) return;
    int l = i / (128 * 512);
    int r = i % (128 * 512);
    int k = r / 512, n = r % 512;
    float w = (n < 256) ? mW1[(size_t)(l * 272 + k) * HH + n]
                        : mW1[(size_t)(l * 272 + 128 + k) * HH + (n - 256)];
    __nv_bfloat16 wh = __float2bfloat16_rn(w);
    g_Wpq_h[i] = wh;
    g_Wpq_l[i] = __float2bfloat16_rn(w - __bfloat162float(wh));
}
__global__ void __launch_bounds__(256) split_uw_kernel(
    const float* __restrict__ uW1, const float* __restrict__ uW2)
{
    int i = blockIdx.x * blockDim.x + threadIdx.x;
    if (i < NL * HH * HH) {
        float w = uW1[i];
        __nv_bfloat16 wh = __float2bfloat16_rn(w);
        g_uW1h[i] = wh;
        g_uW1l[i] = __float2bfloat16_rn(w - __bfloat162float(wh));
    }
    if (i < NL * HH * DD) {
        float w = uW2[i];
        __nv_bfloat16 wh = __float2bfloat16_rn(w);
        g_uW2h[i] = wh;
        g_uW2l[i] = __float2bfloat16_rn(w - __bfloat162float(wh));
    }
}

// ---------------- embedding MLP: 26 -> 128 -> silu -> 128 -------------------
__global__ void __launch_bounds__(128) embed_kernel(
    const float* __restrict__ x, const float* __restrict__ W1,
    const float* __restrict__ b1, const float* __restrict__ W2,
    const float* __restrict__ b2)
{
    __shared__ float xs[4][FIN];
    __shared__ float hid[4][DD];
    int t = threadIdx.x;
    int n0 = blockIdx.x * 4;
    for (int i = t; i < 4 * FIN; i += 128)
        xs[i / FIN][i % FIN] = x[(size_t)n0 * FIN + i];
    __syncthreads();
    float b1t = b1[t];
    #pragma unroll
    for (int nd = 0; nd < 4; nd++) {
        float acc = b1t;
        #pragma unroll
        for (int k = 0; k < FIN; k++) acc += xs[nd][k] * W1[k * DD + t];
        hid[nd][t] = silu_f(acc);
    }
    __syncthreads();
    float b2t = b2[t];
    #pragma unroll
    for (int nd = 0; nd < 4; nd++) {
        float acc = b2t;
        for (int k = 0; k < DD; k++) acc += hid[nd][k] * W2[k * DD + t];
        g_h[(size_t)(n0 + nd) * DD + t] = acc;
    }
}

// ---------------- edge RBF ---------------------------------------------------
__global__ void __launch_bounds__(256) rbf_kernel(
    const float* __restrict__ pos, const int* __restrict__ ei)
{
    int e = blockIdx.x * blockDim.x + threadIdx.x;
    if (e >= EE) return;
    int s  = ei[e];
    int dd = ei[EE + e];
    float dx = pos[dd * 3 + 0] - pos[s * 3 + 0];
    float dy = pos[dd * 3 + 1] - pos[s * 3 + 1];
    float dz = pos[dd * 3 + 2] - pos[s * 3 + 2];
    float d = sqrtf(dx * dx + dy * dy + dz * dz + 1e-12f);
    float env = (d < 10.f) ? 0.5f * (cosf(0.31415926535897932f * d) + 1.f) : 0.f;
    #pragma unroll
    for (int i = 0; i < NRBF; i++) {
        float c = (10.f / 15.f) * (float)i;
        float u = d - c;
        g_ef[(size_t)e * NRBF + i] = env * __expf(-u * u * 1.28f);
    }
}

// ---------------- degree count -----------------------------------------------
__global__ void __launch_bounds__(256) zero_deg_kernel()
{
    int i = blockIdx.x * blockDim.x + threadIdx.x;
    if (i < NN) g_degf[i] = 0.f;
}
__global__ void __launch_bounds__(256) deg_kernel(const int* __restrict__ ei)
{
    int e = blockIdx.x * blockDim.x + threadIdx.x;
    if (e < EE) atomicAdd(&g_degf[ei[EE + e]], 1.f);
}

// ---------------- pq (tensor-core): [P|Q][64][512] = h[64][128] @ Wpq --------
#define PQ_A_LD 136
#define PQ_W_LD 136
#define PQ_SMEM (64 * PQ_A_LD * 2 * 2 + 64 * PQ_W_LD * 2 * 2)   // 69632 B

__global__ void __launch_bounds__(256) pq_mma_kernel(const float* __restrict__ b1, int l)
{
    extern __shared__ char smc[];
    __nv_bfloat16* Ah = (__nv_bfloat16*)smc;                       // 64*136
    __nv_bfloat16* Al = (__nv_bfloat16*)(smc + 64 * PQ_A_LD * 2);
    __nv_bfloat16* Wh = (__nv_bfloat16*)(smc + 64 * PQ_A_LD * 4);
    __nv_bfloat16* Wl = (__nv_bfloat16*)(smc + 64 * PQ_A_LD * 4 + 64 * PQ_W_LD * 2);

    int t = threadIdx.x;
    int warp = t >> 5, lane = t & 31;
    int mw = warp & 3, nw = warp >> 2;
    int n0 = blockIdx.x * 64;

    // load h[64][128] fp32 -> split bf16 hi/lo
    const float4* hp = (const float4*)(g_h + (size_t)n0 * DD);
    #pragma unroll
    for (int j = 0; j < 8; j++) {
        int i = t + j * 256;           // 2048 float4
        int node = i >> 5;
        int k4 = (i & 31) << 2;
        float4 v = hp[i];
        uint32_t h01, l01, h23, l23;
        split2(v.x, v.y, h01, l01);
        split2(v.z, v.w, h23, l23);
        *(uint32_t*)(Ah + node * PQ_A_LD + k4)     = h01;
        *(uint32_t*)(Ah + node * PQ_A_LD + k4 + 2) = h23;
        *(uint32_t*)(Al + node * PQ_A_LD + k4)     = l01;
        *(uint32_t*)(Al + node * PQ_A_LD + k4 + 2) = l23;
    }

    uint32_t a_row = (uint32_t)(mw * 16 + (lane & 15));
    uint32_t a_kh  = (uint32_t)((lane >> 4) << 3);
    uint32_t ah_base = smem_u32(Ah), al_base = smem_u32(Al);
    uint32_t b_krow = (uint32_t)(lane & 15);
    uint32_t b_noff = (uint32_t)(nw * 64 + ((lane >> 4) << 3));
    uint32_t wh_base = smem_u32(Wh), wl_base = smem_u32(Wl);

    const __nv_bfloat16* wpqh = g_Wpq_h + (size_t)l * 128 * 512;
    const __nv_bfloat16* wpql = g_Wpq_l + (size_t)l * 128 * 512;

    int r0 = mw * 16 + (lane >> 2);
    int r1 = r0 + 8;

    for (int nc = 0; nc < 512; nc += 128) {
        float acc[8][4];
        #pragma unroll
        for (int n = 0; n < 8; n++)
            #pragma unroll
            for (int c = 0; c < 4; c++) acc[n][c] = 0.f;

        for (int kc = 0; kc < 128; kc += 64) {
            __syncthreads();
            #pragma unroll
            for (int j = 0; j < 8; j++) {
                int i = t + j * 256;       // 2048 uint2 over [64][128]
                int kk = i >> 5;
                int n4 = (i & 31) << 2;
                *(uint2*)(Wh + kk * PQ_W_LD + n4) =
                    *(const uint2*)(wpqh + (size_t)(kc + kk) * 512 + nc + n4);
                *(uint2*)(Wl + kk * PQ_W_LD + n4) =
                    *(const uint2*)(wpql + (size_t)(kc + kk) * 512 + nc + n4);
            }
            __syncthreads();

            #pragma unroll
            for (int ks = 0; ks < 4; ks++) {
                uint32_t k = (uint32_t)(kc + ks * 16);
                uint32_t ah0, ah1, ah2, ah3, al0, al1, al2, al3;
                ldsm_x4(ah0, ah1, ah2, ah3, ah_base + (a_row * PQ_A_LD + k + a_kh) * 2);
                ldsm_x4(al0, al1, al2, al3, al_base + (a_row * PQ_A_LD + k + a_kh) * 2);
                #pragma unroll
                for (int np = 0; np < 4; np++) {
                    uint32_t off = (((uint32_t)(ks * 16) + b_krow) * PQ_W_LD
                                    + b_noff + (uint32_t)(np * 16)) * 2;
                    uint32_t bh0, bh1, bh2, bh3, bl0, bl1, bl2, bl3;
                    ldsm_x4_t(bh0, bh1, bh2, bh3, wh_base + off);
                    ldsm_x4_t(bl0, bl1, bl2, bl3, wl_base + off);
                    float* a0 = acc[np * 2 + 0];
                    float* a1 = acc[np * 2 + 1];
                    mma_bf16(a0, ah0, ah1, ah2, ah3, bh0, bh1);
                    mma_bf16(a0, al0, al1, al2, al3, bh0, bh1);
                    mma_bf16(a0, ah0, ah1, ah2, ah3, bl0, bl1);
                    mma_bf16(a1, ah0, ah1, ah2, ah3, bh2, bh3);
                    mma_bf16(a1, al0, al1, al2, al3, bh2, bh3);
                    mma_bf16(a1, ah0, ah1, ah2, ah3, bl2, bl3);
                }
            }
        }

        // epilogue for this n-chunk
        #pragma unroll
        for (int n = 0; n < 8; n++) {
            int c = nc + nw * 64 + n * 8 + (lane & 3) * 2;   // 0..511
            float b0v = 0.f, b1v = 0.f;
            float* d0;
            float* d1;
            if (c < 256) {
                b0v = b1[l * HH + c];
                b1v = b1[l * HH + c + 1];
                d0 = g_P + (size_t)(n0 + r0) * HH + c;
                d1 = g_P + (size_t)(n0 + r1) * HH + c;
            } else {
                d0 = g_Q + (size_t)(n0 + r0) * HH + (c - 256);
                d1 = g_Q + (size_t)(n0 + r1) * HH + (c - 256);
            }
            *(float2*)d0 = make_float2(acc[n][0] + b0v, acc[n][1] + b1v);
            *(float2*)d1 = make_float2(acc[n][2] + b0v, acc[n][3] + b1v);
        }
    }
}

// ---------------- zero S ------------------------------------------------------
__global__ void zero_S_kernel()
{
    int i = blockIdx.x * blockDim.x + threadIdx.x;
    ((float4*)g_S)[i] = make_float4(0.f, 0.f, 0.f, 0.f);
}
__global__ void zero_gsum_kernel()
{
    int i = blockIdx.x * blockDim.x + threadIdx.x;
    if (i < BG * DD) g_gsum[i] = 0.f;
}

// ---------------- edge kernel: S[dst] += silu(P[src]+Q[dst]+ef@W1c) ----------
#define EPC 128   // edges per CTA

__global__ void __launch_bounds__(256) edge_kernel(
    const int* __restrict__ ei, const float* __restrict__ W1, int l)
{
    __shared__ float W1c[16 * HH];      // 16 KB
    __shared__ float efs[EPC * NRBF];   // 8 KB
    __shared__ int   sidx[2 * EPC];     // 1 KB

    int t = threadIdx.x;
    int e0 = blockIdx.x * EPC;

    if (t < EPC)            sidx[t] = ei[e0 + t];
    else if (t < 2 * EPC)   sidx[t] = ei[EE + e0 + (t - EPC)];
    for (int i = t; i < EPC * NRBF; i += 256) efs[i] = g_ef[(size_t)e0 * NRBF + i];
    const float* w1c_g = W1 + ((size_t)l * 272 + 256) * HH;
    for (int i = t; i < 16 * HH; i += 256) W1c[i] = w1c_g[i];
    __syncthreads();

    int eq = t >> 6;            // 0..3 (4 edges in flight)
    int k0 = (t & 63) << 2;     // 0..252 step 4

    for (int eb = 0; eb < EPC; eb += 4) {
        int e = eb + eq;
        int s  = sidx[e];
        int dd = sidx[EPC + e];
        float4 z = *(const float4*)(g_P + (size_t)s * HH + k0);
        float4 q = *(const float4*)(g_Q + (size_t)dd * HH + k0);
        z.x += q.x; z.y += q.y; z.z += q.z; z.w += q.w;
        #pragma unroll
        for (int j = 0; j < NRBF; j++) {
            float ev = efs[e * NRBF + j];
            float4 w = *(const float4*)(W1c + j * HH + k0);
            z.x += ev * w.x; z.y += ev * w.y; z.z += ev * w.z; z.w += ev * w.w;
        }
        red_v4(g_S + (size_t)dd * HH + k0,
               silu_f(z.x), silu_f(z.y), silu_f(z.z), silu_f(z.w));
    }
}

// ---------------- agg = S @ W2 + deg * b2  (N x 256 x 128, SIMT) -------------
__global__ void __launch_bounds__(256) agg_kernel(
    const float* __restrict__ W2, const float* __restrict__ b2, int l)
{
    __shared__ float Ss[32 * HH];   // 32 KB
    int t = threadIdx.x;
    int n0 = blockIdx.x * 32;
    for (int i = t; i < 32 * HH / 4; i += 256)
        ((float4*)Ss)[i] = ((const float4*)(g_S + (size_t)n0 * HH))[i];
    __syncthreads();

    int ng = t >> 5;     // 0..7 -> nodes ng*4..+3
    int cg = t & 31;     // cols cg*4..+3
    int c0 = cg * 4;
    float bv[4];
    #pragma unroll
    for (int c = 0; c < 4; c++) bv[c] = b2[l * DD + c0 + c];

    float acc[4][4];
    #pragma unroll
    for (int r = 0; r < 4; r++) {
        float dg = g_degf[n0 + ng * 4 + r];
        #pragma unroll
        for (int c = 0; c < 4; c++) acc[r][c] = dg * bv[c];
    }

    const float* w2p = W2 + (size_t)l * HH * DD + c0;
    for (int k = 0; k < HH; k++) {
        float4 w = *(const float4*)(w2p + (size_t)k * DD);
        float a[4];
        #pragma unroll
        for (int r = 0; r < 4; r++) a[r] = Ss[(ng * 4 + r) * HH + k];
        float wa[4] = {w.x, w.y, w.z, w.w};
        #pragma unroll
        for (int r = 0; r < 4; r++)
            #pragma unroll
            for (int c = 0; c < 4; c++) acc[r][c] += a[r] * wa[c];
    }
    #pragma unroll
    for (int r = 0; r < 4; r++) {
        int n = n0 + ng * 4 + r;
        *(float4*)(g_agg + (size_t)n * DD + c0) =
            make_float4(acc[r][0], acc[r][1], acc[r][2], acc[r][3]);
    }
}

// ---------------- upd (tensor-core): [h|agg] -> 256 -> silu -> 128, resid ----
#define UP_A_LD 264
#define UP_W_LD 264
#define UP_SMEM (32 * UP_A_LD * 2 * 2 + 32 * UP_W_LD * 2 * 2)   // 67584 B

__global__ void __launch_bounds__(256) upd_mma_kernel(
    const float* __restrict__ b1, const float* __restrict__ b2, int l)
{
    extern __shared__ char smc[];
    __nv_bfloat16* Ah = (__nv_bfloat16*)smc;                        // 32*264
    __nv_bfloat16* Al = (__nv_bfloat16*)(smc + 32 * UP_A_LD * 2);
    __nv_bfloat16* Wh = (__nv_bfloat16*)(smc + 32 * UP_A_LD * 4);
    __nv_bfloat16* Wl = (__nv_bfloat16*)(smc + 32 * UP_A_LD * 4 + 32 * UP_W_LD * 2);

    int t = threadIdx.x;
    int warp = t >> 5, lane = t & 31;
    int mw = warp & 1, nwx = warp >> 1;     // 2 m-warps x 4 n-warps
    int n0 = blockIdx.x * 32;

    // load u_in = [h | agg] [32][256] fp32 -> split bf16
    {
        const float4* hp = (const float4*)(g_h + (size_t)n0 * DD);
        const float4* ap = (const float4*)(g_agg + (size_t)n0 * DD);
        #pragma unroll
        for (int j = 0; j < 4; j++) {
            int i = t + j * 256;           // 1024 float4 per source
            int node = i >> 5;
            int k4 = (i & 31) << 2;
            float4 v = hp[i];
            uint32_t h01, l01, h23, l23;
            split2(v.x, v.y, h01, l01);
            split2(v.z, v.w, h23, l23);
            *(uint32_t*)(Ah + node * UP_A_LD + k4)     = h01;
            *(uint32_t*)(Ah + node * UP_A_LD + k4 + 2) = h23;
            *(uint32_t*)(Al + node * UP_A_LD + k4)     = l01;
            *(uint32_t*)(Al + node * UP_A_LD + k4 + 2) = l23;
            float4 w = ap[i];
            split2(w.x, w.y, h01, l01);
            split2(w.z, w.w, h23, l23);
            *(uint32_t*)(Ah + node * UP_A_LD + 128 + k4)     = h01;
            *(uint32_t*)(Ah + node * UP_A_LD + 128 + k4 + 2) = h23;
            *(uint32_t*)(Al + node * UP_A_LD + 128 + k4)     = l01;
            *(uint32_t*)(Al + node * UP_A_LD + 128 + k4 + 2) = l23;
        }
    }

    uint32_t a_row = (uint32_t)(mw * 16 + (lane & 15));
    uint32_t a_kh  = (uint32_t)((lane >> 4) << 3);
    uint32_t ah_base = smem_u32(Ah), al_base = smem_u32(Al);
    uint32_t b_krow = (uint32_t)(lane & 15);
    uint32_t wh_base = smem_u32(Wh), wl_base = smem_u32(Wl);

    int r0 = mw * 16 + (lane >> 2);
    int r1 = r0 + 8;

    // ---- GEMM1: hid[32][256] = u_in @ uW1 + b1, silu ----
    float acc1[8][4];
    #pragma unroll
    for (int n = 0; n < 8; n++)
        #pragma unroll
        for (int c = 0; c < 4; c++) acc1[n][c] = 0.f;

    uint32_t b_noff1 = (uint32_t)(nwx * 64 + ((lane >> 4) << 3));
    const __nv_bfloat16* w1h = g_uW1h + (size_t)l * HH * HH;
    const __nv_bfloat16* w1l = g_uW1l + (size_t)l * HH * HH;

    for (int kc = 0; kc < HH; kc += 32) {
        __syncthreads();
        #pragma unroll
        for (int j = 0; j < 8; j++) {
            int i = t + j * 256;        // 2048 uint2 over [32][256]
            int kk = i >> 6;
            int n4 = (i & 63) << 2;
            *(uint2*)(Wh + kk * UP_W_LD + n4) =
                *(const uint2*)(w1h + (size_t)(kc + kk) * HH + n4);
            *(uint2*)(Wl + kk * UP_W_LD + n4) =
                *(const uint2*)(w1l + (size_t)(kc + kk) * HH + n4);
        }
        __syncthreads();

        #pragma unroll
        for (int ks = 0; ks < 2; ks++) {
            uint32_t k = (uint32_t)(kc + ks * 16);
            uint32_t ah0, ah1, ah2, ah3, al0, al1, al2, al3;
            ldsm_x4(ah0, ah1, ah2, ah3, ah_base + (a_row * UP_A_LD + k + a_kh) * 2);
            ldsm_x4(al0, al1, al2, al3, al_base + (a_row * UP_A_LD + k + a_kh) * 2);
            #pragma unroll
            for (int np = 0; np < 4; np++) {
                uint32_t off = (((uint32_t)(ks * 16) + b_krow) * UP_W_LD
                                + b_noff1 + (uint32_t)(np * 16)) * 2;
                uint32_t bh0, bh1, bh2, bh3, bl0, bl1, bl2, bl3;
                ldsm_x4_t(bh0, bh1, bh2, bh3, wh_base + off);
                ldsm_x4_t(bl0, bl1, bl2, bl3, wl_base + off);
                float* a0 = acc1[np * 2 + 0];
                float* a1 = acc1[np * 2 + 1];
                mma_bf16(a0, ah0, ah1, ah2, ah3, bh0, bh1);
                mma_bf16(a0, al0, al1, al2, al3, bh0, bh1);
                mma_bf16(a0, ah0, ah1, ah2, ah3, bl0, bl1);
                mma_bf16(a1, ah0, ah1, ah2, ah3, bh2, bh3);
                mma_bf16(a1, al0, al1, al2, al3, bh2, bh3);
                mma_bf16(a1, ah0, ah1, ah2, ah3, bl2, bl3);
            }
        }
    }

    // epilogue GEMM1: silu + re-split into A buffer (hidden)
    __syncthreads();    // all warps done reading u_in from A
    #pragma unroll
    for (int n = 0; n < 8; n++) {
        int c = nwx * 64 + n * 8 + (lane & 3) * 2;
        float bb0 = b1[l * HH + c];
        float bb1 = b1[l * HH + c + 1];
        float v00 = silu_f(acc1[n][0] + bb0);
        float v01 = silu_f(acc1[n][1] + bb1);
        float v10 = silu_f(acc1[n][2] + bb0);
        float v11 = silu_f(acc1[n][3] + bb1);
        uint32_t hi, lo;
        split2(v00, v01, hi, lo);
        *(uint32_t*)(Ah + r0 * UP_A_LD + c) = hi;
        *(uint32_t*)(Al + r0 * UP_A_LD + c) = lo;
        split2(v10, v11, hi, lo);
        *(uint32_t*)(Ah + r1 * UP_A_LD + c) = hi;
        *(uint32_t*)(Al + r1 * UP_A_LD + c) = lo;
    }
    __syncthreads();

    // ---- GEMM2: dh[32][128] = hid @ uW2; h += dh + b2 ----
    float acc2[4][4];
    #pragma unroll
    for (int n = 0; n < 4; n++)
        #pragma unroll
        for (int c = 0; c < 4; c++) acc2[n][c] = 0.f;

    uint32_t b_noff2 = (uint32_t)(nwx * 32 + ((lane >> 4) << 3));
    const __nv_bfloat16* w2h = g_uW2h + (size_t)l * HH * DD;
    const __nv_bfloat16* w2l = g_uW2l + (size_t)l * HH * DD;

    for (int kc = 0; kc < HH; kc += 32) {
        __syncthreads();
        #pragma unroll
        for (int j = 0; j < 4; j++) {
            int i = t + j * 256;        // 1024 uint2 over [32][128]
            int kk = i >> 5;
            int n4 = (i & 31) << 2;
            *(uint2*)(Wh + kk * UP_W_LD + n4) =
                *(const uint2*)(w2h + (size_t)(kc + kk) * DD + n4);
            *(uint2*)(Wl + kk * UP_W_LD + n4) =
                *(const uint2*)(w2l + (size_t)(kc + kk) * DD + n4);
        }
        __syncthreads();

        #pragma unroll
        for (int ks = 0; ks < 2; ks++) {
            uint32_t k = (uint32_t)(kc + ks * 16);
            uint32_t ah0, ah1, ah2, ah3, al0, al1, al2, al3;
            ldsm_x4(ah0, ah1, ah2, ah3, ah_base + (a_row * UP_A_LD + k + a_kh) * 2);
            ldsm_x4(al0, al1, al2, al3, al_base + (a_row * UP_A_LD + k + a_kh) * 2);
            #pragma unroll
            for (int np = 0; np < 2; np++) {
                uint32_t off = (((uint32_t)(ks * 16) + b_krow) * UP_W_LD
                                + b_noff2 + (uint32_t)(np * 16)) * 2;
                uint32_t bh0, bh1, bh2, bh3, bl0, bl1, bl2, bl3;
                ldsm_x4_t(bh0, bh1, bh2, bh3, wh_base + off);
                ldsm_x4_t(bl0, bl1, bl2, bl3, wl_base + off);
                float* a0 = acc2[np * 2 + 0];
                float* a1 = acc2[np * 2 + 1];
                mma_bf16(a0, ah0, ah1, ah2, ah3, bh0, bh1);
                mma_bf16(a0, al0, al1, al2, al3, bh0, bh1);
                mma_bf16(a0, ah0, ah1, ah2, ah3, bl0, bl1);
                mma_bf16(a1, ah0, ah1, ah2, ah3, bh2, bh3);
                mma_bf16(a1, al0, al1, al2, al3, bh2, bh3);
                mma_bf16(a1, ah0, ah1, ah2, ah3, bl2, bl3);
            }
        }
    }

    // epilogue: residual add into g_h
    #pragma unroll
    for (int n = 0; n < 4; n++) {
        int c = nwx * 32 + n * 8 + (lane & 3) * 2;
        float bb0 = b2[l * DD + c];
        float bb1 = b2[l * DD + c + 1];
        float* p0 = g_h + (size_t)(n0 + r0) * DD + c;
        float* p1 = g_h + (size_t)(n0 + r1) * DD + c;
        float2 o0 = *(float2*)p0;
        float2 o1 = *(float2*)p1;
        *(float2*)p0 = make_float2(o0.x + acc2[n][0] + bb0, o0.y + acc2[n][1] + bb1);
        *(float2*)p1 = make_float2(o1.x + acc2[n][2] + bb0, o1.y + acc2[n][3] + bb1);
    }
}

// ---------------- readout ----------------------------------------------------
__global__ void __launch_bounds__(128) accum_kernel(const int* __restrict__ batch)
{
    int c = threadIdx.x;
    int n0 = blockIdx.x * 64;
    int curb = batch[n0];
    float s = 0.f;
    for (int i = 0; i < 64; i++) {
        int n = n0 + i;
        int b = batch[n];
        if (b != curb) { atomicAdd(&g_gsum[curb * DD + c], s); s = 0.f; curb = b; }
        s += g_h[(size_t)n * DD + c];
    }
    atomicAdd(&g_gsum[curb * DD + c], s);
}

__global__ void __launch_bounds__(256) final_kernel(
    const int* __restrict__ batch,
    const float* __restrict__ rW1, const float* __restrict__ rb1,
    const float* __restrict__ rW2, const float* __restrict__ rb2,
    float* __restrict__ out)
{
    __shared__ int cnt[BG];
    __shared__ float gs[BG * DD];
    __shared__ float hid[BG * HH];
    int t = threadIdx.x;
    if (t < BG) cnt[t] = 0;
    __syncthreads();
    for (int i = t; i < NN; i += 256) atomicAdd(&cnt[batch[i]], 1);
    __syncthreads();
    for (int i = t; i < BG * DD; i += 256) {
        int b = i / DD;
        gs[i] = g_gsum[i] / (float)max(cnt[b], 1);
    }
    __syncthreads();
    for (int gr = 0; gr < BG; gr++) {
        float a = rb1[t];
        for (int k = 0; k < DD; k++) a += gs[gr * DD + k] * rW1[k * HH + t];
        hid[gr * HH + t] = silu_f(a);
    }
    __syncthreads();
    for (int idx = t; idx < BG * NOUT; idx += 256) {
        int gr = idx >> 6;
        int c  = idx & 63;
        float a = rb2[c];
        for (int k = 0; k < HH; k++) a += hid[gr * HH + k] * rW2[k * NOUT + c];
        out[idx] = a;
    }
}

// ---------------- launch -----------------------------------------------------
extern "C" void kernel_launch(void* const* d_in, const int* in_sizes, int n_in,
                              void* d_out, int out_size)
{
    const float* pos   = (const float*)d_in[0];
    const float* nf    = (const float*)d_in[1];
    const int*   ei    = (const int*)  d_in[2];
    const int*   batch = (const int*)  d_in[3];
    const float* eW1 = (const float*)d_in[4];
    const float* eb1 = (const float*)d_in[5];
    const float* eW2 = (const float*)d_in[6];
    const float* eb2 = (const float*)d_in[7];
    const float* mW1 = (const float*)d_in[8];
    const float* mb1 = (const float*)d_in[9];
    const float* mW2 = (const float*)d_in[10];
    const float* mb2 = (const float*)d_in[11];
    const float* uW1 = (const float*)d_in[12];
    const float* ub1 = (const float*)d_in[13];
    const float* uW2 = (const float*)d_in[14];
    const float* ub2 = (const float*)d_in[15];
    const float* rW1 = (const float*)d_in[16];
    const float* rb1 = (const float*)d_in[17];
    const float* rW2 = (const float*)d_in[18];
    const float* rb2 = (const float*)d_in[19];
    float* out = (float*)d_out;

    cudaFuncSetAttribute(pq_mma_kernel,
                         cudaFuncAttributeMaxDynamicSharedMemorySize, PQ_SMEM);
    cudaFuncSetAttribute(upd_mma_kernel,
                         cudaFuncAttributeMaxDynamicSharedMemorySize, UP_SMEM);

    embed_kernel<<<NN / 4, 128>>>(nf, eW1, eb1, eW2, eb2);
    rbf_kernel<<<EE / 256, 256>>>(pos, ei);
    zero_deg_kernel<<<NN / 256, 256>>>();
    deg_kernel<<<EE / 256, 256>>>(ei);
    split_wpq_kernel<<<(NL * 128 * 512 + 255) / 256, 256>>>(mW1);
    split_uw_kernel<<<(NL * HH * HH + 255) / 256, 256>>>(uW1, uW2);

    for (int l = 0; l < NL; l++) {
        pq_mma_kernel<<<NN / 64, 256, PQ_SMEM>>>(mb1, l);
        zero_S_kernel<<<NN * HH / 4 / 256, 256>>>();
        edge_kernel<<<EE / EPC, 256>>>(ei, mW1, l);
        agg_kernel<<<NN / 32, 256>>>(mW2, mb2, l);
        upd_mma_kernel<<<NN / 32, 256, UP_SMEM>>>(ub1, ub2, l);
    }

    zero_gsum_kernel<<<4, 256>>>();
    accum_kernel<<<NN / 64, 128>>>(batch);
    final_kernel<<<1, 256>>>(batch, rW1, rb1, rW2, rb2, out);
}

// round 10
// speedup vs baseline: 4.3479x; 1.0630x over previous
#include <cuda_runtime.h>
#include <cuda_bf16.h>
#include <cstdint>

#define NN 16384
#define EE 524288
#define BG 8
#define FIN 26
#define DD 128
#define HH 256
#define NOUT 64
#define NL 4
#define NRBF 16

// ---------------- device scratch (statically allocated; no cudaMalloc) -------
__device__ float g_h[NN * DD];        // node features (residual stream)
__device__ float g_P[NN * HH];        // h @ W1a + b1
__device__ float g_Q[NN * HH];        // h @ W1b
__device__ float g_ef[EE * NRBF];     // edge RBF features
__device__ float g_S[NN * HH];        // sum of silu(z) per dst node
__device__ float g_agg[NN * DD];      // message aggregation (= S@W2 + deg*b2)
__device__ float g_degf[NN];          // per-node in-degree (float)
__device__ float g_gsum[BG * DD];     // per-graph sums
// pre-split bf16 weights (hi/lo Markidis pairs)
__device__ __nv_bfloat16 g_Wpq_h[NL * 128 * 512];  // [W1a|W1b] concat on N
__device__ __nv_bfloat16 g_Wpq_l[NL * 128 * 512];
__device__ __nv_bfloat16 g_uW1h[NL * HH * HH];
__device__ __nv_bfloat16 g_uW1l[NL * HH * HH];
__device__ __nv_bfloat16 g_uW2h[NL * HH * DD];
__device__ __nv_bfloat16 g_uW2l[NL * HH * DD];
__device__ __nv_bfloat16 g_mW2h[NL * HH * DD];
__device__ __nv_bfloat16 g_mW2l[NL * HH * DD];

__device__ __forceinline__ float silu_f(float x) {
    return x * __frcp_rn(1.f + __expf(-x));
}

__device__ __forceinline__ void red_v4(float* p, float a, float b, float c, float d) {
    asm volatile("red.global.add.v4.f32 [%0], {%1,%2,%3,%4};"
                 :: "l"(p), "f"(a), "f"(b), "f"(c), "f"(d) : "memory");
}

// ---------------- mma.sync helpers ------------------------------------------
__device__ __forceinline__ uint32_t smem_u32(const void* p) {
    return (uint32_t)__cvta_generic_to_shared(p);
}
__device__ __forceinline__ void ldsm_x4(uint32_t& r0, uint32_t& r1,
                                        uint32_t& r2, uint32_t& r3, uint32_t a) {
    asm volatile("ldmatrix.sync.aligned.m8n8.x4.shared.b16 {%0,%1,%2,%3}, [%4];"
                 : "=r"(r0), "=r"(r1), "=r"(r2), "=r"(r3) : "r"(a));
}
__device__ __forceinline__ void ldsm_x4_t(uint32_t& r0, uint32_t& r1,
                                          uint32_t& r2, uint32_t& r3, uint32_t a) {
    asm volatile("ldmatrix.sync.aligned.m8n8.x4.trans.shared.b16 {%0,%1,%2,%3}, [%4];"
                 : "=r"(r0), "=r"(r1), "=r"(r2), "=r"(r3) : "r"(a));
}
__device__ __forceinline__ void mma_bf16(float* d, uint32_t a0, uint32_t a1,
                                         uint32_t a2, uint32_t a3,
                                         uint32_t b0, uint32_t b1) {
    asm volatile(
        "mma.sync.aligned.m16n8k16.row.col.f32.bf16.bf16.f32 "
        "{%0,%1,%2,%3}, {%4,%5,%6,%7}, {%8,%9}, {%0,%1,%2,%3};"
        : "+f"(d[0]), "+f"(d[1]), "+f"(d[2]), "+f"(d[3])
        : "r"(a0), "r"(a1), "r"(a2), "r"(a3), "r"(b0), "r"(b1));
}
// pack two floats into (hi-u32, lo-u32) bf16x2 Markidis pairs
__device__ __forceinline__ void split2(float f0, float f1, uint32_t& hi, uint32_t& lo) {
    __nv_bfloat16 h0 = __float2bfloat16_rn(f0);
    __nv_bfloat16 h1 = __float2bfloat16_rn(f1);
    __nv_bfloat16 l0 = __float2bfloat16_rn(f0 - __bfloat162float(h0));
    __nv_bfloat16 l1 = __float2bfloat16_rn(f1 - __bfloat162float(h1));
    hi = (uint32_t)__bfloat16_as_ushort(h0) | ((uint32_t)__bfloat16_as_ushort(h1) << 16);
    lo = (uint32_t)__bfloat16_as_ushort(l0) | ((uint32_t)__bfloat16_as_ushort(l1) << 16);
}

// ---------------- weight pre-split kernels -----------------------------------
__global__ void __launch_bounds__(256) split_wpq_kernel(const float* __restrict__ mW1)
{
    int i = blockIdx.x * blockDim.x + threadIdx.x;
    if (i >= NL * 128 * 512) return;
    int l = i / (128 * 512);
    int r = i % (128 * 512);
    int k = r / 512, n = r % 512;
    float w = (n < 256) ? mW1[(size_t)(l * 272 + k) * HH + n]
                        : mW1[(size_t)(l * 272 + 128 + k) * HH + (n - 256)];
    __nv_bfloat16 wh = __float2bfloat16_rn(w);
    g_Wpq_h[i] = wh;
    g_Wpq_l[i] = __float2bfloat16_rn(w - __bfloat162float(wh));
}
__global__ void __launch_bounds__(256) split_uw_kernel(
    const float* __restrict__ uW1, const float* __restrict__ uW2,
    const float* __restrict__ mW2)
{
    int i = blockIdx.x * blockDim.x + threadIdx.x;
    if (i < NL * HH * HH) {
        float w = uW1[i];
        __nv_bfloat16 wh = __float2bfloat16_rn(w);
        g_uW1h[i] = wh;
        g_uW1l[i] = __float2bfloat16_rn(w - __bfloat162float(wh));
    }
    if (i < NL * HH * DD) {
        float w = uW2[i];
        __nv_bfloat16 wh = __float2bfloat16_rn(w);
        g_uW2h[i] = wh;
        g_uW2l[i] = __float2bfloat16_rn(w - __bfloat162float(wh));
        float m = mW2[i];
        __nv_bfloat16 mh = __float2bfloat16_rn(m);
        g_mW2h[i] = mh;
        g_mW2l[i] = __float2bfloat16_rn(m - __bfloat162float(mh));
    }
}

// ---------------- embedding MLP: 26 -> 128 -> silu -> 128 -------------------
__global__ void __launch_bounds__(128) embed_kernel(
    const float* __restrict__ x, const float* __restrict__ W1,
    const float* __restrict__ b1, const float* __restrict__ W2,
    const float* __restrict__ b2)
{
    __shared__ float xs[4][FIN];
    __shared__ float hid[4][DD];
    int t = threadIdx.x;
    int n0 = blockIdx.x * 4;
    for (int i = t; i < 4 * FIN; i += 128)
        xs[i / FIN][i % FIN] = x[(size_t)n0 * FIN + i];
    __syncthreads();
    float b1t = b1[t];
    #pragma unroll
    for (int nd = 0; nd < 4; nd++) {
        float acc = b1t;
        #pragma unroll
        for (int k = 0; k < FIN; k++) acc += xs[nd][k] * W1[k * DD + t];
        hid[nd][t] = silu_f(acc);
    }
    __syncthreads();
    float b2t = b2[t];
    #pragma unroll
    for (int nd = 0; nd < 4; nd++) {
        float acc = b2t;
        for (int k = 0; k < DD; k++) acc += hid[nd][k] * W2[k * DD + t];
        g_h[(size_t)(n0 + nd) * DD + t] = acc;
    }
}

// ---------------- edge RBF ---------------------------------------------------
__global__ void __launch_bounds__(256) rbf_kernel(
    const float* __restrict__ pos, const int* __restrict__ ei)
{
    int e = blockIdx.x * blockDim.x + threadIdx.x;
    if (e >= EE) return;
    int s  = ei[e];
    int dd = ei[EE + e];
    float dx = pos[dd * 3 + 0] - pos[s * 3 + 0];
    float dy = pos[dd * 3 + 1] - pos[s * 3 + 1];
    float dz = pos[dd * 3 + 2] - pos[s * 3 + 2];
    float d = sqrtf(dx * dx + dy * dy + dz * dz + 1e-12f);
    float env = (d < 10.f) ? 0.5f * (cosf(0.31415926535897932f * d) + 1.f) : 0.f;
    #pragma unroll
    for (int i = 0; i < NRBF; i++) {
        float c = (10.f / 15.f) * (float)i;
        float u = d - c;
        g_ef[(size_t)e * NRBF + i] = env * __expf(-u * u * 1.28f);
    }
}

// ---------------- degree count -----------------------------------------------
__global__ void __launch_bounds__(256) zero_deg_kernel()
{
    int i = blockIdx.x * blockDim.x + threadIdx.x;
    if (i < NN) g_degf[i] = 0.f;
}
__global__ void __launch_bounds__(256) deg_kernel(const int* __restrict__ ei)
{
    int e = blockIdx.x * blockDim.x + threadIdx.x;
    if (e < EE) atomicAdd(&g_degf[ei[EE + e]], 1.f);
}

// ---------------- pq (tensor-core): [P|Q][64][512] = h[64][128] @ Wpq --------
#define PQ_A_LD 136
#define PQ_W_LD 136
#define PQ_SMEM (64 * PQ_A_LD * 2 * 2 + 64 * PQ_W_LD * 2 * 2)   // 69632 B

__global__ void __launch_bounds__(256) pq_mma_kernel(const float* __restrict__ b1, int l)
{
    extern __shared__ char smc[];
    __nv_bfloat16* Ah = (__nv_bfloat16*)smc;                       // 64*136
    __nv_bfloat16* Al = (__nv_bfloat16*)(smc + 64 * PQ_A_LD * 2);
    __nv_bfloat16* Wh = (__nv_bfloat16*)(smc + 64 * PQ_A_LD * 4);
    __nv_bfloat16* Wl = (__nv_bfloat16*)(smc + 64 * PQ_A_LD * 4 + 64 * PQ_W_LD * 2);

    int t = threadIdx.x;
    int warp = t >> 5, lane = t & 31;
    int mw = warp & 3, nw = warp >> 2;
    int n0 = blockIdx.x * 64;

    // load h[64][128] fp32 -> split bf16 hi/lo
    const float4* hp = (const float4*)(g_h + (size_t)n0 * DD);
    #pragma unroll
    for (int j = 0; j < 8; j++) {
        int i = t + j * 256;           // 2048 float4
        int node = i >> 5;
        int k4 = (i & 31) << 2;
        float4 v = hp[i];
        uint32_t h01, l01, h23, l23;
        split2(v.x, v.y, h01, l01);
        split2(v.z, v.w, h23, l23);
        *(uint32_t*)(Ah + node * PQ_A_LD + k4)     = h01;
        *(uint32_t*)(Ah + node * PQ_A_LD + k4 + 2) = h23;
        *(uint32_t*)(Al + node * PQ_A_LD + k4)     = l01;
        *(uint32_t*)(Al + node * PQ_A_LD + k4 + 2) = l23;
    }

    uint32_t a_row = (uint32_t)(mw * 16 + (lane & 15));
    uint32_t a_kh  = (uint32_t)((lane >> 4) << 3);
    uint32_t ah_base = smem_u32(Ah), al_base = smem_u32(Al);
    uint32_t b_krow = (uint32_t)(lane & 15);
    uint32_t b_noff = (uint32_t)(nw * 64 + ((lane >> 4) << 3));
    uint32_t wh_base = smem_u32(Wh), wl_base = smem_u32(Wl);

    const __nv_bfloat16* wpqh = g_Wpq_h + (size_t)l * 128 * 512;
    const __nv_bfloat16* wpql = g_Wpq_l + (size_t)l * 128 * 512;

    int r0 = mw * 16 + (lane >> 2);
    int r1 = r0 + 8;

    for (int nc = 0; nc < 512; nc += 128) {
        float acc[8][4];
        #pragma unroll
        for (int n = 0; n < 8; n++)
            #pragma unroll
            for (int c = 0; c < 4; c++) acc[n][c] = 0.f;

        for (int kc = 0; kc < 128; kc += 64) {
            __syncthreads();
            #pragma unroll
            for (int j = 0; j < 8; j++) {
                int i = t + j * 256;       // 2048 uint2 over [64][128]
                int kk = i >> 5;
                int n4 = (i & 31) << 2;
                *(uint2*)(Wh + kk * PQ_W_LD + n4) =
                    *(const uint2*)(wpqh + (size_t)(kc + kk) * 512 + nc + n4);
                *(uint2*)(Wl + kk * PQ_W_LD + n4) =
                    *(const uint2*)(wpql + (size_t)(kc + kk) * 512 + nc + n4);
            }
            __syncthreads();

            #pragma unroll
            for (int ks = 0; ks < 4; ks++) {
                uint32_t k = (uint32_t)(kc + ks * 16);
                uint32_t ah0, ah1, ah2, ah3, al0, al1, al2, al3;
                ldsm_x4(ah0, ah1, ah2, ah3, ah_base + (a_row * PQ_A_LD + k + a_kh) * 2);
                ldsm_x4(al0, al1, al2, al3, al_base + (a_row * PQ_A_LD + k + a_kh) * 2);
                #pragma unroll
                for (int np = 0; np < 4; np++) {
                    uint32_t off = (((uint32_t)(ks * 16) + b_krow) * PQ_W_LD
                                    + b_noff + (uint32_t)(np * 16)) * 2;
                    uint32_t bh0, bh1, bh2, bh3, bl0, bl1, bl2, bl3;
                    ldsm_x4_t(bh0, bh1, bh2, bh3, wh_base + off);
                    ldsm_x4_t(bl0, bl1, bl2, bl3, wl_base + off);
                    float* a0 = acc[np * 2 + 0];
                    float* a1 = acc[np * 2 + 1];
                    mma_bf16(a0, ah0, ah1, ah2, ah3, bh0, bh1);
                    mma_bf16(a0, al0, al1, al2, al3, bh0, bh1);
                    mma_bf16(a0, ah0, ah1, ah2, ah3, bl0, bl1);
                    mma_bf16(a1, ah0, ah1, ah2, ah3, bh2, bh3);
                    mma_bf16(a1, al0, al1, al2, al3, bh2, bh3);
                    mma_bf16(a1, ah0, ah1, ah2, ah3, bl2, bl3);
                }
            }
        }

        // epilogue for this n-chunk
        #pragma unroll
        for (int n = 0; n < 8; n++) {
            int c = nc + nw * 64 + n * 8 + (lane & 3) * 2;   // 0..511
            float b0v = 0.f, b1v = 0.f;
            float* d0;
            float* d1;
            if (c < 256) {
                b0v = b1[l * HH + c];
                b1v = b1[l * HH + c + 1];
                d0 = g_P + (size_t)(n0 + r0) * HH + c;
                d1 = g_P + (size_t)(n0 + r1) * HH + c;
            } else {
                d0 = g_Q + (size_t)(n0 + r0) * HH + (c - 256);
                d1 = g_Q + (size_t)(n0 + r1) * HH + (c - 256);
            }
            *(float2*)d0 = make_float2(acc[n][0] + b0v, acc[n][1] + b1v);
            *(float2*)d1 = make_float2(acc[n][2] + b0v, acc[n][3] + b1v);
        }
    }
}

// ---------------- zero S ------------------------------------------------------
__global__ void zero_S_kernel()
{
    int i = blockIdx.x * blockDim.x + threadIdx.x;
    ((float4*)g_S)[i] = make_float4(0.f, 0.f, 0.f, 0.f);
}
__global__ void zero_gsum_kernel()
{
    int i = blockIdx.x * blockDim.x + threadIdx.x;
    if (i < BG * DD) g_gsum[i] = 0.f;
}

// ---------------- edge kernel: S[dst] += silu(P[src]+Q[dst]+ef@W1c) ----------
// W1c slice register-cached per thread (64 floats): zero LDS traffic for W1c.
#define EPC 128   // edges per CTA

__global__ void __launch_bounds__(256) edge_kernel(
    const int* __restrict__ ei, const float* __restrict__ W1, int l)
{
    __shared__ float efs[EPC * NRBF];   // 8 KB
    __shared__ int   sidx[2 * EPC];     // 1 KB

    int t = threadIdx.x;
    int e0 = blockIdx.x * EPC;

    if (t < EPC)            sidx[t] = ei[e0 + t];
    else if (t < 2 * EPC)   sidx[t] = ei[EE + e0 + (t - EPC)];
    for (int i = t; i < EPC * NRBF; i += 256) efs[i] = g_ef[(size_t)e0 * NRBF + i];

    int eq = t >> 6;            // 0..3 (4 edges in flight)
    int k0 = (t & 63) << 2;     // 0..252 step 4

    // register-cache this thread's W1c columns: W1c[j][k0..k0+3]
    const float* w1c_g = W1 + ((size_t)l * 272 + 256) * HH;
    float4 wreg[NRBF];
    #pragma unroll
    for (int j = 0; j < NRBF; j++)
        wreg[j] = *(const float4*)(w1c_g + j * HH + k0);
    __syncthreads();

    #pragma unroll 2
    for (int eb = 0; eb < EPC; eb += 4) {
        int e = eb + eq;
        int s  = sidx[e];
        int dd = sidx[EPC + e];
        float4 z = *(const float4*)(g_P + (size_t)s * HH + k0);
        float4 q = *(const float4*)(g_Q + (size_t)dd * HH + k0);
        z.x += q.x; z.y += q.y; z.z += q.z; z.w += q.w;
        #pragma unroll
        for (int j = 0; j < NRBF; j++) {
            float ev = efs[e * NRBF + j];
            z.x += ev * wreg[j].x; z.y += ev * wreg[j].y;
            z.z += ev * wreg[j].z; z.w += ev * wreg[j].w;
        }
        red_v4(g_S + (size_t)dd * HH + k0,
               silu_f(z.x), silu_f(z.y), silu_f(z.z), silu_f(z.w));
    }
}

// ---------------- agg (tensor-core): agg[32][128] = S[32][256]@W2 + deg*b2 ---
#define AG_A_LD 264
#define AG_W_LD 136
#define AG_SMEM (32 * AG_A_LD * 2 * 2 + 32 * AG_W_LD * 2 * 2)   // 51200 B

__global__ void __launch_bounds__(256) agg_mma_kernel(const float* __restrict__ b2, int l)
{
    extern __shared__ char smc[];
    __nv_bfloat16* Ah = (__nv_bfloat16*)smc;                        // 32*264
    __nv_bfloat16* Al = (__nv_bfloat16*)(smc + 32 * AG_A_LD * 2);
    __nv_bfloat16* Wh = (__nv_bfloat16*)(smc + 32 * AG_A_LD * 4);
    __nv_bfloat16* Wl = (__nv_bfloat16*)(smc + 32 * AG_A_LD * 4 + 32 * AG_W_LD * 2);

    int t = threadIdx.x;
    int warp = t >> 5, lane = t & 31;
    int mw = warp & 1, nwx = warp >> 1;     // 2 m-warps x 4 n-warps
    int n0 = blockIdx.x * 32;

    // load S[32][256] fp32 -> split bf16
    const float4* sp = (const float4*)(g_S + (size_t)n0 * HH);
    #pragma unroll
    for (int j = 0; j < 8; j++) {
        int i = t + j * 256;           // 2048 float4
        int node = i >> 6;
        int k4 = (i & 63) << 2;
        float4 v = sp[i];
        uint32_t h01, l01, h23, l23;
        split2(v.x, v.y, h01, l01);
        split2(v.z, v.w, h23, l23);
        *(uint32_t*)(Ah + node * AG_A_LD + k4)     = h01;
        *(uint32_t*)(Ah + node * AG_A_LD + k4 + 2) = h23;
        *(uint32_t*)(Al + node * AG_A_LD + k4)     = l01;
        *(uint32_t*)(Al + node * AG_A_LD + k4 + 2) = l23;
    }

    uint32_t a_row = (uint32_t)(mw * 16 + (lane & 15));
    uint32_t a_kh  = (uint32_t)((lane >> 4) << 3);
    uint32_t ah_base = smem_u32(Ah), al_base = smem_u32(Al);
    uint32_t b_krow = (uint32_t)(lane & 15);
    uint32_t b_noff = (uint32_t)(nwx * 32 + ((lane >> 4) << 3));
    uint32_t wh_base = smem_u32(Wh), wl_base = smem_u32(Wl);

    const __nv_bfloat16* w2h = g_mW2h + (size_t)l * HH * DD;
    const __nv_bfloat16* w2l = g_mW2l + (size_t)l * HH * DD;

    float acc[4][4];
    #pragma unroll
    for (int n = 0; n < 4; n++)
        #pragma unroll
        for (int c = 0; c < 4; c++) acc[n][c] = 0.f;

    for (int kc = 0; kc < HH; kc += 32) {
        __syncthreads();
        #pragma unroll
        for (int j = 0; j < 4; j++) {
            int i = t + j * 256;        // 1024 uint2 over [32][128]
            int kk = i >> 5;
            int n4 = (i & 31) << 2;
            *(uint2*)(Wh + kk * AG_W_LD + n4) =
                *(const uint2*)(w2h + (size_t)(kc + kk) * DD + n4);
            *(uint2*)(Wl + kk * AG_W_LD + n4) =
                *(const uint2*)(w2l + (size_t)(kc + kk) * DD + n4);
        }
        __syncthreads();

        #pragma unroll
        for (int ks = 0; ks < 2; ks++) {
            uint32_t k = (uint32_t)(kc + ks * 16);
            uint32_t ah0, ah1, ah2, ah3, al0, al1, al2, al3;
            ldsm_x4(ah0, ah1, ah2, ah3, ah_base + (a_row * AG_A_LD + k + a_kh) * 2);
            ldsm_x4(al0, al1, al2, al3, al_base + (a_row * AG_A_LD + k + a_kh) * 2);
            #pragma unroll
            for (int np = 0; np < 2; np++) {
                uint32_t off = (((uint32_t)(ks * 16) + b_krow) * AG_W_LD
                                + b_noff + (uint32_t)(np * 16)) * 2;
                uint32_t bh0, bh1, bh2, bh3, bl0, bl1, bl2, bl3;
                ldsm_x4_t(bh0, bh1, bh2, bh3, wh_base + off);
                ldsm_x4_t(bl0, bl1, bl2, bl3, wl_base + off);
                float* a0 = acc[np * 2 + 0];
                float* a1 = acc[np * 2 + 1];
                mma_bf16(a0, ah0, ah1, ah2, ah3, bh0, bh1);
                mma_bf16(a0, al0, al1, al2, al3, bh0, bh1);
                mma_bf16(a0, ah0, ah1, ah2, ah3, bl0, bl1);
                mma_bf16(a1, ah0, ah1, ah2, ah3, bh2, bh3);
                mma_bf16(a1, al0, al1, al2, al3, bh2, bh3);
                mma_bf16(a1, ah0, ah1, ah2, ah3, bl2, bl3);
            }
        }
    }

    int r0 = mw * 16 + (lane >> 2);
    int r1 = r0 + 8;
    float dg0 = g_degf[n0 + r0];
    float dg1 = g_degf[n0 + r1];
    #pragma unroll
    for (int n = 0; n < 4; n++) {
        int c = nwx * 32 + n * 8 + (lane & 3) * 2;
        float bb0 = b2[l * DD + c];
        float bb1 = b2[l * DD + c + 1];
        *(float2*)(g_agg + (size_t)(n0 + r0) * DD + c) =
            make_float2(acc[n][0] + dg0 * bb0, acc[n][1] + dg0 * bb1);
        *(float2*)(g_agg + (size_t)(n0 + r1) * DD + c) =
            make_float2(acc[n][2] + dg1 * bb0, acc[n][3] + dg1 * bb1);
    }
}

// ---------------- upd (tensor-core): [h|agg] -> 256 -> silu -> 128, resid ----
#define UP_A_LD 264
#define UP_W_LD 264
#define UP_SMEM (32 * UP_A_LD * 2 * 2 + 32 * UP_W_LD * 2 * 2)   // 67584 B

__global__ void __launch_bounds__(256) upd_mma_kernel(
    const float* __restrict__ b1, const float* __restrict__ b2, int l)
{
    extern __shared__ char smc[];
    __nv_bfloat16* Ah = (__nv_bfloat16*)smc;                        // 32*264
    __nv_bfloat16* Al = (__nv_bfloat16*)(smc + 32 * UP_A_LD * 2);
    __nv_bfloat16* Wh = (__nv_bfloat16*)(smc + 32 * UP_A_LD * 4);
    __nv_bfloat16* Wl = (__nv_bfloat16*)(smc + 32 * UP_A_LD * 4 + 32 * UP_W_LD * 2);

    int t = threadIdx.x;
    int warp = t >> 5, lane = t & 31;
    int mw = warp & 1, nwx = warp >> 1;     // 2 m-warps x 4 n-warps
    int n0 = blockIdx.x * 32;

    // load u_in = [h | agg] [32][256] fp32 -> split bf16
    {
        const float4* hp = (const float4*)(g_h + (size_t)n0 * DD);
        const float4* ap = (const float4*)(g_agg + (size_t)n0 * DD);
        #pragma unroll
        for (int j = 0; j < 4; j++) {
            int i = t + j * 256;           // 1024 float4 per source
            int node = i >> 5;
            int k4 = (i & 31) << 2;
            float4 v = hp[i];
            uint32_t h01, l01, h23, l23;
            split2(v.x, v.y, h01, l01);
            split2(v.z, v.w, h23, l23);
            *(uint32_t*)(Ah + node * UP_A_LD + k4)     = h01;
            *(uint32_t*)(Ah + node * UP_A_LD + k4 + 2) = h23;
            *(uint32_t*)(Al + node * UP_A_LD + k4)     = l01;
            *(uint32_t*)(Al + node * UP_A_LD + k4 + 2) = l23;
            float4 w = ap[i];
            split2(w.x, w.y, h01, l01);
            split2(w.z, w.w, h23, l23);
            *(uint32_t*)(Ah + node * UP_A_LD + 128 + k4)     = h01;
            *(uint32_t*)(Ah + node * UP_A_LD + 128 + k4 + 2) = h23;
            *(uint32_t*)(Al + node * UP_A_LD + 128 + k4)     = l01;
            *(uint32_t*)(Al + node * UP_A_LD + 128 + k4 + 2) = l23;
        }
    }

    uint32_t a_row = (uint32_t)(mw * 16 + (lane & 15));
    uint32_t a_kh  = (uint32_t)((lane >> 4) << 3);
    uint32_t ah_base = smem_u32(Ah), al_base = smem_u32(Al);
    uint32_t b_krow = (uint32_t)(lane & 15);
    uint32_t wh_base = smem_u32(Wh), wl_base = smem_u32(Wl);

    int r0 = mw * 16 + (lane >> 2);
    int r1 = r0 + 8;

    // ---- GEMM1: hid[32][256] = u_in @ uW1 + b1, silu ----
    float acc1[8][4];
    #pragma unroll
    for (int n = 0; n < 8; n++)
        #pragma unroll
        for (int c = 0; c < 4; c++) acc1[n][c] = 0.f;

    uint32_t b_noff1 = (uint32_t)(nwx * 64 + ((lane >> 4) << 3));
    const __nv_bfloat16* w1h = g_uW1h + (size_t)l * HH * HH;
    const __nv_bfloat16* w1l = g_uW1l + (size_t)l * HH * HH;

    for (int kc = 0; kc < HH; kc += 32) {
        __syncthreads();
        #pragma unroll
        for (int j = 0; j < 8; j++) {
            int i = t + j * 256;        // 2048 uint2 over [32][256]
            int kk = i >> 6;
            int n4 = (i & 63) << 2;
            *(uint2*)(Wh + kk * UP_W_LD + n4) =
                *(const uint2*)(w1h + (size_t)(kc + kk) * HH + n4);
            *(uint2*)(Wl + kk * UP_W_LD + n4) =
                *(const uint2*)(w1l + (size_t)(kc + kk) * HH + n4);
        }
        __syncthreads();

        #pragma unroll
        for (int ks = 0; ks < 2; ks++) {
            uint32_t k = (uint32_t)(kc + ks * 16);
            uint32_t ah0, ah1, ah2, ah3, al0, al1, al2, al3;
            ldsm_x4(ah0, ah1, ah2, ah3, ah_base + (a_row * UP_A_LD + k + a_kh) * 2);
            ldsm_x4(al0, al1, al2, al3, al_base + (a_row * UP_A_LD + k + a_kh) * 2);
            #pragma unroll
            for (int np = 0; np < 4; np++) {
                uint32_t off = (((uint32_t)(ks * 16) + b_krow) * UP_W_LD
                                + b_noff1 + (uint32_t)(np * 16)) * 2;
                uint32_t bh0, bh1, bh2, bh3, bl0, bl1, bl2, bl3;
                ldsm_x4_t(bh0, bh1, bh2, bh3, wh_base + off);
                ldsm_x4_t(bl0, bl1, bl2, bl3, wl_base + off);
                float* a0 = acc1[np * 2 + 0];
                float* a1 = acc1[np * 2 + 1];
                mma_bf16(a0, ah0, ah1, ah2, ah3, bh0, bh1);
                mma_bf16(a0, al0, al1, al2, al3, bh0, bh1);
                mma_bf16(a0, ah0, ah1, ah2, ah3, bl0, bl1);
                mma_bf16(a1, ah0, ah1, ah2, ah3, bh2, bh3);
                mma_bf16(a1, al0, al1, al2, al3, bh2, bh3);
                mma_bf16(a1, ah0, ah1, ah2, ah3, bl2, bl3);
            }
        }
    }

    // epilogue GEMM1: silu + re-split into A buffer (hidden)
    __syncthreads();    // all warps done reading u_in from A
    #pragma unroll
    for (int n = 0; n < 8; n++) {
        int c = nwx * 64 + n * 8 + (lane & 3) * 2;
        float bb0 = b1[l * HH + c];
        float bb1 = b1[l * HH + c + 1];
        float v00 = silu_f(acc1[n][0] + bb0);
        float v01 = silu_f(acc1[n][1] + bb1);
        float v10 = silu_f(acc1[n][2] + bb0);
        float v11 = silu_f(acc1[n][3] + bb1);
        uint32_t hi, lo;
        split2(v00, v01, hi, lo);
        *(uint32_t*)(Ah + r0 * UP_A_LD + c) = hi;
        *(uint32_t*)(Al + r0 * UP_A_LD + c) = lo;
        split2(v10, v11, hi, lo);
        *(uint32_t*)(Ah + r1 * UP_A_LD + c) = hi;
        *(uint32_t*)(Al + r1 * UP_A_LD + c) = lo;
    }
    __syncthreads();

    // ---- GEMM2: dh[32][128] = hid @ uW2; h += dh + b2 ----
    float acc2[4][4];
    #pragma unroll
    for (int n = 0; n < 4; n++)
        #pragma unroll
        for (int c = 0; c < 4; c++) acc2[n][c] = 0.f;

    uint32_t b_noff2 = (uint32_t)(nwx * 32 + ((lane >> 4) << 3));
    const __nv_bfloat16* w2h = g_uW2h + (size_t)l * HH * DD;
    const __nv_bfloat16* w2l = g_uW2l + (size_t)l * HH * DD;

    for (int kc = 0; kc < HH; kc += 32) {
        __syncthreads();
        #pragma unroll
        for (int j = 0; j < 4; j++) {
            int i = t + j * 256;        // 1024 uint2 over [32][128]
            int kk = i >> 5;
            int n4 = (i & 31) << 2;
            *(uint2*)(Wh + kk * UP_W_LD + n4) =
                *(const uint2*)(w2h + (size_t)(kc + kk) * DD + n4);
            *(uint2*)(Wl + kk * UP_W_LD + n4) =
                *(const uint2*)(w2l + (size_t)(kc + kk) * DD + n4);
        }
        __syncthreads();

        #pragma unroll
        for (int ks = 0; ks < 2; ks++) {
            uint32_t k = (uint32_t)(kc + ks * 16);
            uint32_t ah0, ah1, ah2, ah3, al0, al1, al2, al3;
            ldsm_x4(ah0, ah1, ah2, ah3, ah_base + (a_row * UP_A_LD + k + a_kh) * 2);
            ldsm_x4(al0, al1, al2, al3, al_base + (a_row * UP_A_LD + k + a_kh) * 2);
            #pragma unroll
            for (int np = 0; np < 2; np++) {
                uint32_t off = (((uint32_t)(ks * 16) + b_krow) * UP_W_LD
                                + b_noff2 + (uint32_t)(np * 16)) * 2;
                uint32_t bh0, bh1, bh2, bh3, bl0, bl1, bl2, bl3;
                ldsm_x4_t(bh0, bh1, bh2, bh3, wh_base + off);
                ldsm_x4_t(bl0, bl1, bl2, bl3, wl_base + off);
                float* a0 = acc2[np * 2 + 0];
                float* a1 = acc2[np * 2 + 1];
                mma_bf16(a0, ah0, ah1, ah2, ah3, bh0, bh1);
                mma_bf16(a0, al0, al1, al2, al3, bh0, bh1);
                mma_bf16(a0, ah0, ah1, ah2, ah3, bl0, bl1);
                mma_bf16(a1, ah0, ah1, ah2, ah3, bh2, bh3);
                mma_bf16(a1, al0, al1, al2, al3, bh2, bh3);
                mma_bf16(a1, ah0, ah1, ah2, ah3, bl2, bl3);
            }
        }
    }

    // epilogue: residual add into g_h
    #pragma unroll
    for (int n = 0; n < 4; n++) {
        int c = nwx * 32 + n * 8 + (lane & 3) * 2;
        float bb0 = b2[l * DD + c];
        float bb1 = b2[l * DD + c + 1];
        float* p0 = g_h + (size_t)(n0 + r0) * DD + c;
        float* p1 = g_h + (size_t)(n0 + r1) * DD + c;
        float2 o0 = *(float2*)p0;
        float2 o1 = *(float2*)p1;
        *(float2*)p0 = make_float2(o0.x + acc2[n][0] + bb0, o0.y + acc2[n][1] + bb1);
        *(float2*)p1 = make_float2(o1.x + acc2[n][2] + bb0, o1.y + acc2[n][3] + bb1);
    }
}

// ---------------- readout ----------------------------------------------------
__global__ void __launch_bounds__(128) accum_kernel(const int* __restrict__ batch)
{
    int c = threadIdx.x;
    int n0 = blockIdx.x * 64;
    int curb = batch[n0];
    float s = 0.f;
    for (int i = 0; i < 64; i++) {
        int n = n0 + i;
        int b = batch[n];
        if (b != curb) { atomicAdd(&g_gsum[curb * DD + c], s); s = 0.f; curb = b; }
        s += g_h[(size_t)n * DD + c];
    }
    atomicAdd(&g_gsum[curb * DD + c], s);
}

__global__ void __launch_bounds__(256) final_kernel(
    const int* __restrict__ batch,
    const float* __restrict__ rW1, const float* __restrict__ rb1,
    const float* __restrict__ rW2, const float* __restrict__ rb2,
    float* __restrict__ out)
{
    __shared__ int cnt[BG];
    __shared__ float gs[BG * DD];
    __shared__ float hid[BG * HH];
    int t = threadIdx.x;
    if (t < BG) cnt[t] = 0;
    __syncthreads();
    for (int i = t; i < NN; i += 256) atomicAdd(&cnt[batch[i]], 1);
    __syncthreads();
    for (int i = t; i < BG * DD; i += 256) {
        int b = i / DD;
        gs[i] = g_gsum[i] / (float)max(cnt[b], 1);
    }
    __syncthreads();
    for (int gr = 0; gr < BG; gr++) {
        float a = rb1[t];
        for (int k = 0; k < DD; k++) a += gs[gr * DD + k] * rW1[k * HH + t];
        hid[gr * HH + t] = silu_f(a);
    }
    __syncthreads();
    for (int idx = t; idx < BG * NOUT; idx += 256) {
        int gr = idx >> 6;
        int c  = idx & 63;
        float a = rb2[c];
        for (int k = 0; k < HH; k++) a += hid[gr * HH + k] * rW2[k * NOUT + c];
        out[idx] = a;
    }
}

// ---------------- launch -----------------------------------------------------
extern "C" void kernel_launch(void* const* d_in, const int* in_sizes, int n_in,
                              void* d_out, int out_size)
{
    const float* pos   = (const float*)d_in[0];
    const float* nf    = (const float*)d_in[1];
    const int*   ei    = (const int*)  d_in[2];
    const int*   batch = (const int*)  d_in[3];
    const float* eW1 = (const float*)d_in[4];
    const float* eb1 = (const float*)d_in[5];
    const float* eW2 = (const float*)d_in[6];
    const float* eb2 = (const float*)d_in[7];
    const float* mW1 = (const float*)d_in[8];
    const float* mb1 = (const float*)d_in[9];
    const float* mW2 = (const float*)d_in[10];
    const float* mb2 = (const float*)d_in[11];
    const float* uW1 = (const float*)d_in[12];
    const float* ub1 = (const float*)d_in[13];
    const float* uW2 = (const float*)d_in[14];
    const float* ub2 = (const float*)d_in[15];
    const float* rW1 = (const float*)d_in[16];
    const float* rb1 = (const float*)d_in[17];
    const float* rW2 = (const float*)d_in[18];
    const float* rb2 = (const float*)d_in[19];
    float* out = (float*)d_out;

    cudaFuncSetAttribute(pq_mma_kernel,
                         cudaFuncAttributeMaxDynamicSharedMemorySize, PQ_SMEM);
    cudaFuncSetAttribute(agg_mma_kernel,
                         cudaFuncAttributeMaxDynamicSharedMemorySize, AG_SMEM);
    cudaFuncSetAttribute(upd_mma_kernel,
                         cudaFuncAttributeMaxDynamicSharedMemorySize, UP_SMEM);

    embed_kernel<<<NN / 4, 128>>>(nf, eW1, eb1, eW2, eb2);
    rbf_kernel<<<EE / 256, 256>>>(pos, ei);
    zero_deg_kernel<<<NN / 256, 256>>>();
    deg_kernel<<<EE / 256, 256>>>(ei);
    split_wpq_kernel<<<(NL * 128 * 512 + 255) / 256, 256>>>(mW1);
    split_uw_kernel<<<(NL * HH * HH + 255) / 256, 256>>>(uW1, uW2, mW2);

    for (int l = 0; l < NL; l++) {
        pq_mma_kernel<<<NN / 64, 256, PQ_SMEM>>>(mb1, l);
        zero_S_kernel<<<NN * HH / 4 / 256, 256>>>();
        edge_kernel<<<EE / EPC, 256>>>(ei, mW1, l);
        agg_mma_kernel<<<NN / 32, 256, AG_SMEM>>>(mb2, l);
        upd_mma_kernel<<<NN / 32, 256, UP_SMEM>>>(ub1, ub2, l);
    }

    zero_gsum_kernel<<<4, 256>>>();
    accum_kernel<<<NN / 64, 128>>>(batch);
    final_kernel<<<1, 256>>>(batch, rW1, rb1, rW2, rb2, out);
}